// round 12
// baseline (speedup 1.0000x reference)
#include <cuda_runtime.h>
#include <cuda_bf16.h>
#include <cstdint>
#include <math_constants.h>

constexpr int BATCH = 4, SEQ = 2048, DIM = 1024, MTOT = BATCH * SEQ;

// ---- scratch (device globals; 16B-aligned) ----
__device__ __align__(16) __nv_bfloat16 g_Xhi [(size_t)MTOT * DIM];
__device__ __align__(16) __nv_bfloat16 g_Xlo [(size_t)MTOT * DIM];
__device__ __align__(16) __nv_bfloat16 g_Wth [4][(size_t)DIM * DIM];
__device__ __align__(16) __nv_bfloat16 g_Wtl [4][(size_t)DIM * DIM];
__device__ __align__(16) __nv_bfloat16 g_Qhi [(size_t)MTOT * DIM];
__device__ __align__(16) __nv_bfloat16 g_Qlo [(size_t)MTOT * DIM];
__device__ __align__(16) __nv_bfloat16 g_Khi [(size_t)MTOT * DIM];
__device__ __align__(16) __nv_bfloat16 g_Klo [(size_t)MTOT * DIM];
__device__ __align__(16) __nv_bfloat16 g_Vthi[(size_t)BATCH * DIM * SEQ];
__device__ __align__(16) __nv_bfloat16 g_Vtlo[(size_t)BATCH * DIM * SEQ];
__device__ __align__(16) float         g_S   [(size_t)BATCH * SEQ * SEQ];
__device__ __align__(16) __nv_bfloat16 g_Phi [(size_t)BATCH * SEQ * SEQ];
__device__ __align__(16) __nv_bfloat16 g_Plo [(size_t)BATCH * SEQ * SEQ];
__device__ __align__(16) __nv_bfloat16 g_Ohi [(size_t)MTOT * DIM];
__device__ __align__(16) __nv_bfloat16 g_Olo [(size_t)MTOT * DIM];

__device__ __forceinline__ uint32_t s2u(const void* p) {
    uint32_t a;
    asm("{ .reg .u64 t; cvta.to.shared.u64 t, %1; cvt.u32.u64 %0, t; }" : "=r"(a) : "l"(p));
    return a;
}
#define CPA16(dst, src) \
    asm volatile("cp.async.cg.shared.global [%0], [%1], 16;" :: "r"(dst), "l"(src) : "memory")
#define LDSM4(r, a) \
    asm volatile("ldmatrix.sync.aligned.m8n8.x4.shared.b16 {%0,%1,%2,%3}, [%4];" \
        : "=r"((r)[0]), "=r"((r)[1]), "=r"((r)[2]), "=r"((r)[3]) : "r"(a))
#define MMA16816(c, a, b0, b1) \
    asm volatile("mma.sync.aligned.m16n8k16.row.col.f32.bf16.bf16.f32 " \
        "{%0,%1,%2,%3}, {%4,%5,%6,%7}, {%8,%9}, {%0,%1,%2,%3};" \
        : "+f"((c)[0]), "+f"((c)[1]), "+f"((c)[2]), "+f"((c)[3]) \
        : "r"((a)[0]), "r"((a)[1]), "r"((a)[2]), "r"((a)[3]), "r"(b0), "r"(b1))

// ---- GEMM: D[m][n] = sum_k A[m][k]*B[n][k]; bf16x3 split via mma.sync ----
// CTA 128x128, 8 warps (2x4), warp tile 64x32, K-chunk 32, 5-stage cp.async,
// two stages per barrier (one __syncthreads per 64 K), register fragments
// double-buffered across the 4 k16 slabs of each 64-K window.
constexpr int ROWB = 80;
constexpr int R_AH = 0, R_AL = 10240, R_BH = 20480, R_BL = 30720;
constexpr int STAGE_SZ = 40960;
constexpr int NSTAGE = 5;
constexpr int GEMM_SMEM = NSTAGE * STAGE_SZ;      // 204800

// MODE 0: fp32 out (alpha, opt bias). MODE 1: bf16 hi/lo out. MODE 2: Vt hi/lo out.
template<int MODE, bool HASBIAS>
__global__ __launch_bounds__(256, 1)
void gemm_mma(const __nv_bfloat16* __restrict__ Ah, const __nv_bfloat16* __restrict__ Al,
              const __nv_bfloat16* __restrict__ Bh, const __nv_bfloat16* __restrict__ Bl,
              float* __restrict__ Cf,
              __nv_bfloat16* __restrict__ Ch, __nv_bfloat16* __restrict__ Cl,
              const float* __restrict__ bias,
              int Kd, int ldC, float alpha,
              long long aRowZ, long long bRowZ, long long cOffZ)
{
    extern __shared__ __align__(128) char smem[];
    const uint32_t sb = s2u(smem);
    const int tid = threadIdx.x, wid = tid >> 5, lane = tid & 31;
    const int wm = wid >> 2, wn = wid & 3;
    const int rowBase = blockIdx.y * 128, colBase = blockIdx.x * 128;
    const long long aRow0 = (long long)blockIdx.z * aRowZ + rowBase;
    const long long bRow0 = (long long)blockIdx.z * bRowZ + colBase;

    // cp.async geometry: thread -> (row r=tid/4 in 0..63, granule cg=tid&3)
    const int r = tid >> 2, cg = tid & 3;
    const long long rowStep = (long long)Kd * 2;
    const char* pAH = (const char*)Ah + (aRow0 + r) * rowStep + cg * 16;
    const char* pAL = (const char*)Al + (aRow0 + r) * rowStep + cg * 16;
    const char* pBH = (const char*)Bh + (bRow0 + r) * rowStep + cg * 16;
    const char* pBL = (const char*)Bl + (bRow0 + r) * rowStep + cg * 16;
    const uint32_t dRow = (uint32_t)(r * ROWB + cg * 16);
    const long long rowStep64 = 64 * rowStep;
    const int nCh = Kd >> 5;          // K-chunks of 32 (even for all our K)

    auto load_stage = [&](int c, int s) {
        const uint32_t d = sb + s * STAGE_SZ + dRow;
        const long long cb = (long long)c * 64;
        #pragma unroll
        for (int i = 0; i < 2; i++) {
            CPA16(d + R_AH + i * 64 * ROWB, pAH + i * rowStep64 + cb);
            CPA16(d + R_AL + i * 64 * ROWB, pAL + i * rowStep64 + cb);
            CPA16(d + R_BH + i * 64 * ROWB, pBH + i * rowStep64 + cb);
            CPA16(d + R_BL + i * 64 * ROWB, pBL + i * rowStep64 + cb);
        }
        asm volatile("cp.async.commit_group;" ::: "memory");
    };

    const uint32_t aOff = (uint32_t)((wm * 64 + (lane & 7) + ((lane >> 3) & 1) * 8) * ROWB
                                     + ((lane >> 4) * 8) * 2);
    const uint32_t bOff = (uint32_t)((wn * 32 + (lane & 7) + ((lane >> 4) & 1) * 8) * ROWB
                                     + (((lane >> 3) & 1) * 8) * 2);

    float acc[4][4][4];
    #pragma unroll
    for (int i = 0; i < 4; i++)
        #pragma unroll
        for (int j = 0; j < 4; j++)
            #pragma unroll
            for (int q = 0; q < 4; q++) acc[i][j][q] = 0.0f;

    // double-buffered register fragments
    uint32_t ah[2][4][4], al[2][4][4], bh[2][2][4], bl[2][2][4];

    auto load_frag = [&](int buf, uint32_t st, int k16) {
        #pragma unroll
        for (int mt = 0; mt < 4; mt++) {
            LDSM4(ah[buf][mt], st + R_AH + aOff + mt * (16 * ROWB) + k16 * 32);
            LDSM4(al[buf][mt], st + R_AL + aOff + mt * (16 * ROWB) + k16 * 32);
        }
        #pragma unroll
        for (int j = 0; j < 2; j++) {
            LDSM4(bh[buf][j], st + R_BH + bOff + j * (16 * ROWB) + k16 * 32);
            LDSM4(bl[buf][j], st + R_BL + bOff + j * (16 * ROWB) + k16 * 32);
        }
    };

    auto mma_all = [&](int buf) {
        #pragma unroll
        for (int mt = 0; mt < 4; mt++)
            #pragma unroll
            for (int nt = 0; nt < 4; nt++) {
                const int jj = nt >> 1, hh = (nt & 1) * 2;
                MMA16816(acc[mt][nt], ah[buf][mt], bh[buf][jj][hh], bh[buf][jj][hh + 1]);
            }
        #pragma unroll
        for (int mt = 0; mt < 4; mt++)
            #pragma unroll
            for (int nt = 0; nt < 4; nt++) {
                const int jj = nt >> 1, hh = (nt & 1) * 2;
                MMA16816(acc[mt][nt], ah[buf][mt], bl[buf][jj][hh], bl[buf][jj][hh + 1]);
            }
        #pragma unroll
        for (int mt = 0; mt < 4; mt++)
            #pragma unroll
            for (int nt = 0; nt < 4; nt++) {
                const int jj = nt >> 1, hh = (nt & 1) * 2;
                MMA16816(acc[mt][nt], al[buf][mt], bh[buf][jj][hh], bh[buf][jj][hh + 1]);
            }
    };

    // prolog: chunks 0,1,2 -> stages 0,1,2
    load_stage(0, 0);
    load_stage(1, 1);
    load_stage(2, 2);

    int nc = 3, ps = 3;      // next chunk to prefetch and its stage
    int cs = 0;              // stage holding chunk cc

    for (int cc = 0; cc < nCh; cc += 2) {
        if (cc + 2 < nCh) asm volatile("cp.async.wait_group 1;" ::: "memory");
        else              asm volatile("cp.async.wait_group 0;" ::: "memory");
        __syncthreads();
        #pragma unroll
        for (int j = 0; j < 2; j++) {
            if (nc < nCh) {
                load_stage(nc, ps);
                nc++;
                ps = (ps == NSTAGE - 1) ? 0 : ps + 1;
            }
        }

        const int cs1 = (cs == NSTAGE - 1) ? 0 : cs + 1;
        const uint32_t stb0 = sb + cs * STAGE_SZ;
        const uint32_t stb1 = sb + cs1 * STAGE_SZ;

        // 4 k16 slabs, fragments pipelined one slab ahead
        load_frag(0, stb0, 0);
        load_frag(1, stb0, 1);
        mma_all(0);
        load_frag(0, stb1, 0);
        mma_all(1);
        load_frag(1, stb1, 1);
        mma_all(0);
        mma_all(1);

        cs = (cs1 == NSTAGE - 1) ? 0 : cs1 + 1;
    }

    // ---- epilogue (identical to R11) ----
    if (MODE == 2) {
        const int b = rowBase >> 11;
        const int seq0 = rowBase & 2047;
        const int mloc0 = wm * 64 + (lane >> 2);
        const int nloc0 = wn * 32 + (lane & 3) * 2;
        __nv_bfloat16* smt = reinterpret_cast<__nv_bfloat16*>(smem);
        constexpr int MP = 136;
        #pragma unroll 1
        for (int p = 0; p < 2; p++) {
            __syncthreads();
            #pragma unroll
            for (int mt = 0; mt < 4; mt++)
                #pragma unroll
                for (int nt = 0; nt < 4; nt++)
                    #pragma unroll
                    for (int h = 0; h < 2; h++) {
                        float v0 = acc[mt][nt][h * 2 + 0] * alpha;
                        float v1 = acc[mt][nt][h * 2 + 1] * alpha;
                        __nv_bfloat16 w0, w1;
                        if (p == 0) { w0 = __float2bfloat16(v0); w1 = __float2bfloat16(v1); }
                        else {
                            __nv_bfloat16 h0 = __float2bfloat16(v0), h1 = __float2bfloat16(v1);
                            w0 = __float2bfloat16(v0 - __bfloat162float(h0));
                            w1 = __float2bfloat16(v1 - __bfloat162float(h1));
                        }
                        const int m = mloc0 + mt * 16 + h * 8;
                        const int n = nloc0 + nt * 8;
                        smt[n * MP + m]       = w0;
                        smt[(n + 1) * MP + m] = w1;
                    }
            __syncthreads();
            __nv_bfloat16* dst = p ? Cl : Ch;
            #pragma unroll
            for (int i = 0; i < 8; i++) {
                const int g = tid + i * 256;
                const int n = g >> 4, o = g & 15;
                uint4 val = *reinterpret_cast<const uint4*>(smt + n * MP + o * 8);
                *reinterpret_cast<uint4*>(dst
                    + ((long long)(b * 1024 + colBase + n)) * 2048 + seq0 + o * 8) = val;
            }
        }
    } else {
        const int mBase = rowBase + wm * 64 + (lane >> 2);
        const int nBaseW = colBase + wn * 32 + (lane & 3) * 2;
        #pragma unroll
        for (int mt = 0; mt < 4; mt++)
            #pragma unroll
            for (int nt = 0; nt < 4; nt++) {
                const int n = nBaseW + nt * 8;
                #pragma unroll
                for (int h = 0; h < 2; h++) {
                    const int m = mBase + mt * 16 + h * 8;
                    float v0 = acc[mt][nt][h * 2 + 0] * alpha;
                    float v1 = acc[mt][nt][h * 2 + 1] * alpha;
                    if (MODE == 0) {
                        if (HASBIAS) { v0 += bias[n]; v1 += bias[n + 1]; }
                        float2 w; w.x = v0; w.y = v1;
                        *reinterpret_cast<float2*>(Cf + (long long)blockIdx.z * cOffZ
                            + (long long)m * ldC + n) = w;
                    } else {
                        __nv_bfloat16 h0 = __float2bfloat16(v0), h1 = __float2bfloat16(v1);
                        __nv_bfloat162 hp, lp;
                        hp.x = h0; hp.y = h1;
                        lp.x = __float2bfloat16(v0 - __bfloat162float(h0));
                        lp.y = __float2bfloat16(v1 - __bfloat162float(h1));
                        const long long base = (long long)blockIdx.z * cOffZ
                            + (long long)m * ldC + n;
                        *reinterpret_cast<__nv_bfloat162*>(Ch + base) = hp;
                        *reinterpret_cast<__nv_bfloat162*>(Cl + base) = lp;
                    }
                }
            }
    }
}

// ---- fp32 -> bf16 hi/lo split ----
__global__ __launch_bounds__(256)
void split_kernel(const float4* __restrict__ in, __nv_bfloat162* __restrict__ hi,
                  __nv_bfloat162* __restrict__ lo, int n4)
{
    int i = blockIdx.x * blockDim.x + threadIdx.x;
    if (i >= n4) return;
    float4 v = in[i];
    __nv_bfloat16 hx = __float2bfloat16(v.x), hy = __float2bfloat16(v.y);
    __nv_bfloat16 hz = __float2bfloat16(v.z), hw = __float2bfloat16(v.w);
    __nv_bfloat162 a, b, c, d;
    a.x = hx; a.y = hy; b.x = hz; b.y = hw;
    c.x = __float2bfloat16(v.x - __bfloat162float(hx));
    c.y = __float2bfloat16(v.y - __bfloat162float(hy));
    d.x = __float2bfloat16(v.z - __bfloat162float(hz));
    d.y = __float2bfloat16(v.w - __bfloat162float(hw));
    hi[(size_t)i*2] = a; hi[(size_t)i*2+1] = b;
    lo[(size_t)i*2] = c; lo[(size_t)i*2+1] = d;
}

// ---- all four W[1024][1024] -> Wt hi/lo (transpose + split), z selects ----
__global__ __launch_bounds__(256)
void transpose_split4(const float* __restrict__ w0, const float* __restrict__ w1,
                      const float* __restrict__ w2, const float* __restrict__ w3,
                      __nv_bfloat16* __restrict__ Th, __nv_bfloat16* __restrict__ Tl)
{
    const float* W = blockIdx.z == 0 ? w0 : blockIdx.z == 1 ? w1 : blockIdx.z == 2 ? w2 : w3;
    __nv_bfloat16* oh = Th + (size_t)blockIdx.z * DIM * DIM;
    __nv_bfloat16* ol = Tl + (size_t)blockIdx.z * DIM * DIM;
    __shared__ float t[32][33];
    int x = blockIdx.x * 32 + threadIdx.x;
    int y0 = blockIdx.y * 32;
    #pragma unroll
    for (int j = threadIdx.y; j < 32; j += 8)
        t[j][threadIdx.x] = W[(long long)(y0 + j) * DIM + x];
    __syncthreads();
    int xo = y0 + threadIdx.x, yo = blockIdx.x * 32;
    #pragma unroll
    for (int j = threadIdx.y; j < 32; j += 8) {
        float v = t[threadIdx.x][j];
        __nv_bfloat16 h = __float2bfloat16(v);
        long long idx = (long long)(yo + j) * DIM + xo;
        oh[idx] = h;
        ol[idx] = __float2bfloat16(v - __bfloat162float(h));
    }
}

// ---- softmax over 2048 cols + bf16 hi/lo split of P ----
__global__ __launch_bounds__(256)
void softmax_split_kernel(const float* __restrict__ S,
                          __nv_bfloat16* __restrict__ Ph, __nv_bfloat16* __restrict__ Pl)
{
    const float* row = S + (long long)blockIdx.x * SEQ;
    const int tid = threadIdx.x;
    float v[8], m = -CUDART_INF_F;
    #pragma unroll
    for (int i = 0; i < 8; i++) { v[i] = row[tid + i*256]; m = fmaxf(m, v[i]); }
    __shared__ float red[256];
    red[tid] = m; __syncthreads();
    #pragma unroll
    for (int s = 128; s > 0; s >>= 1) { if (tid < s) red[tid] = fmaxf(red[tid], red[tid+s]); __syncthreads(); }
    m = red[0]; __syncthreads();
    float sum = 0.f;
    #pragma unroll
    for (int i = 0; i < 8; i++) { v[i] = __expf(v[i] - m); sum += v[i]; }
    red[tid] = sum; __syncthreads();
    #pragma unroll
    for (int s = 128; s > 0; s >>= 1) { if (tid < s) red[tid] += red[tid+s]; __syncthreads(); }
    float inv = 1.0f / red[0];
    const long long base = (long long)blockIdx.x * SEQ;
    #pragma unroll
    for (int i = 0; i < 8; i++) {
        float p = v[i] * inv;
        __nv_bfloat16 h = __float2bfloat16(p);
        Ph[base + tid + i*256] = h;
        Pl[base + tid + i*256] = __float2bfloat16(p - __bfloat162float(h));
    }
}

// ---- launch ----
extern "C" void kernel_launch(void* const* d_in, const int* in_sizes, int n_in,
                              void* d_out, int out_size)
{
    const float* X  = (const float*)d_in[0];
    const float* bo = (const float*)d_in[5];
    float* out = (float*)d_out;

    __nv_bfloat16 *Xhi, *Xlo, *Qhi, *Qlo, *Khi, *Klo, *Vthi, *Vtlo, *Phi, *Plo, *Ohi, *Olo;
    __nv_bfloat16 *Wth, *Wtl;
    float* Sc;
    cudaGetSymbolAddress((void**)&Xhi, g_Xhi);   cudaGetSymbolAddress((void**)&Xlo, g_Xlo);
    cudaGetSymbolAddress((void**)&Wth, g_Wth);   cudaGetSymbolAddress((void**)&Wtl, g_Wtl);
    cudaGetSymbolAddress((void**)&Qhi, g_Qhi);   cudaGetSymbolAddress((void**)&Qlo, g_Qlo);
    cudaGetSymbolAddress((void**)&Khi, g_Khi);   cudaGetSymbolAddress((void**)&Klo, g_Klo);
    cudaGetSymbolAddress((void**)&Vthi, g_Vthi); cudaGetSymbolAddress((void**)&Vtlo, g_Vtlo);
    cudaGetSymbolAddress((void**)&Sc, g_S);
    cudaGetSymbolAddress((void**)&Phi, g_Phi);   cudaGetSymbolAddress((void**)&Plo, g_Plo);
    cudaGetSymbolAddress((void**)&Ohi, g_Ohi);   cudaGetSymbolAddress((void**)&Olo, g_Olo);

    cudaFuncSetAttribute(gemm_mma<0,false>, cudaFuncAttributeMaxDynamicSharedMemorySize, GEMM_SMEM);
    cudaFuncSetAttribute(gemm_mma<0,true >, cudaFuncAttributeMaxDynamicSharedMemorySize, GEMM_SMEM);
    cudaFuncSetAttribute(gemm_mma<1,false>, cudaFuncAttributeMaxDynamicSharedMemorySize, GEMM_SMEM);
    cudaFuncSetAttribute(gemm_mma<2,false>, cudaFuncAttributeMaxDynamicSharedMemorySize, GEMM_SMEM);

    const size_t wsz = (size_t)DIM * DIM;

    // 1: X split   2: W transpose+split
    split_kernel<<<(MTOT*DIM/4 + 255)/256, 256>>>((const float4*)X,
        (__nv_bfloat162*)Xhi, (__nv_bfloat162*)Xlo, MTOT*DIM/4);
    transpose_split4<<<dim3(32,32,4), dim3(32,8)>>>((const float*)d_in[1], (const float*)d_in[2],
        (const float*)d_in[3], (const float*)d_in[4], Wth, Wtl);

    // 3-5: Q, K, Vt projections
    {
        dim3 g(DIM/128, MTOT/128, 1);
        gemm_mma<1,false><<<g, 256, GEMM_SMEM>>>(Xhi, Xlo, Wth + 0*wsz, Wtl + 0*wsz,
            nullptr, Qhi, Qlo, nullptr, DIM, DIM, 1.0f, 0, 0, 0);
        gemm_mma<1,false><<<g, 256, GEMM_SMEM>>>(Xhi, Xlo, Wth + 1*wsz, Wtl + 1*wsz,
            nullptr, Khi, Klo, nullptr, DIM, DIM, 1.0f, 0, 0, 0);
        gemm_mma<2,false><<<g, 256, GEMM_SMEM>>>(Xhi, Xlo, Wth + 2*wsz, Wtl + 2*wsz,
            nullptr, Vthi, Vtlo, nullptr, DIM, DIM, 1.0f, 0, 0, 0);
    }

    // 6: scores = (Q @ K^T)/32  (captured by ncu -s 5 -c 1)
    {
        dim3 g(SEQ/128, SEQ/128, BATCH);
        gemm_mma<0,false><<<g, 256, GEMM_SMEM>>>(Qhi, Qlo, Khi, Klo,
            Sc, nullptr, nullptr, nullptr, DIM, SEQ, 1.0f/32.0f,
            (long long)SEQ, (long long)SEQ, (long long)SEQ * SEQ);
    }

    // 7: softmax + split -> P hi/lo
    softmax_split_kernel<<<BATCH*SEQ, 256>>>(Sc, Phi, Plo);

    // 8: O = P @ V  (B = Vt K-major, K=2048)
    {
        dim3 g(DIM/128, SEQ/128, BATCH);
        gemm_mma<1,false><<<g, 256, GEMM_SMEM>>>(Phi, Plo, Vthi, Vtlo,
            nullptr, Ohi, Olo, nullptr, SEQ, DIM, 1.0f,
            (long long)SEQ, (long long)DIM, (long long)SEQ * DIM);
    }

    // 9: out = O @ Wo + bo
    {
        dim3 g(DIM/128, MTOT/128, 1);
        gemm_mma<0,true><<<g, 256, GEMM_SMEM>>>(Ohi, Olo, Wth + 3*wsz, Wtl + 3*wsz,
            out, nullptr, nullptr, bo, DIM, DIM, 1.0f, 0, 0, 0);
    }
}

// round 13
// speedup vs baseline: 1.1676x; 1.1676x over previous
#include <cuda_runtime.h>
#include <cuda_fp16.h>
#include <cstdint>
#include <math_constants.h>

constexpr int BATCH = 4, SEQ = 2048, DIM = 1024, MTOT = BATCH * SEQ;

// ---- scratch (device globals; 16B-aligned) ----
__device__ __align__(16) __half g_Xhi [(size_t)MTOT * DIM];
__device__ __align__(16) __half g_Xlo [(size_t)MTOT * DIM];
__device__ __align__(16) __half g_Wth [4][(size_t)DIM * DIM];
__device__ __align__(16) __half g_Wtl [4][(size_t)DIM * DIM];
__device__ __align__(16) __half g_Qhi [(size_t)MTOT * DIM];
__device__ __align__(16) __half g_Qlo [(size_t)MTOT * DIM];
__device__ __align__(16) __half g_Khi [(size_t)MTOT * DIM];
__device__ __align__(16) __half g_Vthi[(size_t)BATCH * DIM * SEQ];
__device__ __align__(16) float  g_S   [(size_t)BATCH * SEQ * SEQ];
__device__ __align__(16) __half g_Phi [(size_t)BATCH * SEQ * SEQ];
__device__ __align__(16) __half g_Plo [(size_t)BATCH * SEQ * SEQ];
__device__ __align__(16) __half g_Ohi [(size_t)MTOT * DIM];
__device__ __align__(16) __half g_Olo [(size_t)MTOT * DIM];

__device__ __forceinline__ uint32_t s2u(const void* p) {
    uint32_t a;
    asm("{ .reg .u64 t; cvta.to.shared.u64 t, %1; cvt.u32.u64 %0, t; }" : "=r"(a) : "l"(p));
    return a;
}
#define CPA16(dst, src) \
    asm volatile("cp.async.cg.shared.global [%0], [%1], 16;" :: "r"(dst), "l"(src) : "memory")
#define LDSM4(r, a) \
    asm volatile("ldmatrix.sync.aligned.m8n8.x4.shared.b16 {%0,%1,%2,%3}, [%4];" \
        : "=r"((r)[0]), "=r"((r)[1]), "=r"((r)[2]), "=r"((r)[3]) : "r"(a))
#define MMA16816(c, a, b0, b1) \
    asm volatile("mma.sync.aligned.m16n8k16.row.col.f32.f16.f16.f32 " \
        "{%0,%1,%2,%3}, {%4,%5,%6,%7}, {%8,%9}, {%0,%1,%2,%3};" \
        : "+f"((c)[0]), "+f"((c)[1]), "+f"((c)[2]), "+f"((c)[3]) \
        : "r"((a)[0]), "r"((a)[1]), "r"((a)[2]), "r"((a)[3]), "r"(b0), "r"(b1))

// ---- GEMM: D[m][n] = sum_k A[m][k]*B[n][k]; fp16 split via mma.sync ----
// TERMS=3: AhBh + AhBl + AlBh (err ~2^-23). TERMS=2: AhBh + AlBh (B err ~2^-12).
// CTA 128x128, 8 warps (2x4), warp tile 64x32, K-chunk 32, 5-stage cp.async,
// one __syncthreads per 64 K (two stages per barrier). ROWB=80 conflict-free.
constexpr int ROWB = 80;
constexpr int R_AH = 0, R_AL = 10240, R_BH = 20480, R_BL = 30720;
constexpr int STAGE_SZ = 40960;
constexpr int NSTAGE = 5;
constexpr int GEMM_SMEM = NSTAGE * STAGE_SZ;      // 204800

// MODE 0: fp32 out (alpha, opt bias). MODE 1: hi+lo out. MODE 2: Vt hi-only out.
// MODE 3: hi-only out.
template<int MODE, int TERMS, bool HASBIAS>
__global__ __launch_bounds__(256, 1)
void gemm_mma(const __half* __restrict__ Ah, const __half* __restrict__ Al,
              const __half* __restrict__ Bh, const __half* __restrict__ Bl,
              float* __restrict__ Cf,
              __half* __restrict__ Ch, __half* __restrict__ Cl,
              const float* __restrict__ bias,
              int Kd, int ldC, float alpha,
              long long aRowZ, long long bRowZ, long long cOffZ)
{
    extern __shared__ __align__(128) char smem[];
    const uint32_t sb = s2u(smem);
    const int tid = threadIdx.x, wid = tid >> 5, lane = tid & 31;
    const int wm = wid >> 2, wn = wid & 3;
    const int rowBase = blockIdx.y * 128, colBase = blockIdx.x * 128;
    const long long aRow0 = (long long)blockIdx.z * aRowZ + rowBase;
    const long long bRow0 = (long long)blockIdx.z * bRowZ + colBase;

    const int r = tid >> 2, cg = tid & 3;
    const long long rowStep = (long long)Kd * 2;
    const char* pAH = (const char*)Ah + (aRow0 + r) * rowStep + cg * 16;
    const char* pAL = (const char*)Al + (aRow0 + r) * rowStep + cg * 16;
    const char* pBH = (const char*)Bh + (bRow0 + r) * rowStep + cg * 16;
    const char* pBL = (TERMS == 3) ? (const char*)Bl + (bRow0 + r) * rowStep + cg * 16 : nullptr;
    const uint32_t dRow = (uint32_t)(r * ROWB + cg * 16);
    const long long rowStep64 = 64 * rowStep;
    const int nCh = Kd >> 5;

    auto load_stage = [&](int c, int s) {
        const uint32_t d = sb + s * STAGE_SZ + dRow;
        const long long cb = (long long)c * 64;
        #pragma unroll
        for (int i = 0; i < 2; i++) {
            CPA16(d + R_AH + i * 64 * ROWB, pAH + i * rowStep64 + cb);
            CPA16(d + R_AL + i * 64 * ROWB, pAL + i * rowStep64 + cb);
            CPA16(d + R_BH + i * 64 * ROWB, pBH + i * rowStep64 + cb);
            if (TERMS == 3)
                CPA16(d + R_BL + i * 64 * ROWB, pBL + i * rowStep64 + cb);
        }
        asm volatile("cp.async.commit_group;" ::: "memory");
    };

    const uint32_t aOff = (uint32_t)((wm * 64 + (lane & 7) + ((lane >> 3) & 1) * 8) * ROWB
                                     + ((lane >> 4) * 8) * 2);
    const uint32_t bOff = (uint32_t)((wn * 32 + (lane & 7) + ((lane >> 4) & 1) * 8) * ROWB
                                     + (((lane >> 3) & 1) * 8) * 2);

    float acc[4][4][4];
    #pragma unroll
    for (int i = 0; i < 4; i++)
        #pragma unroll
        for (int j = 0; j < 4; j++)
            #pragma unroll
            for (int q = 0; q < 4; q++) acc[i][j][q] = 0.0f;

    load_stage(0, 0);
    load_stage(1, 1);
    load_stage(2, 2);

    int nc = 3, ps = 3;
    int cs = 0;

    for (int cc = 0; cc < nCh; cc += 2) {
        if (cc + 2 < nCh) asm volatile("cp.async.wait_group 1;" ::: "memory");
        else              asm volatile("cp.async.wait_group 0;" ::: "memory");
        __syncthreads();
        #pragma unroll
        for (int j = 0; j < 2; j++) {
            if (nc < nCh) {
                load_stage(nc, ps);
                nc++;
                ps = (ps == NSTAGE - 1) ? 0 : ps + 1;
            }
        }

        #pragma unroll
        for (int half = 0; half < 2; half++) {
            const uint32_t st = sb + cs * STAGE_SZ;
            #pragma unroll
            for (int k16 = 0; k16 < 2; k16++) {
                uint32_t ah[4][4], al[4][4], bh[2][4], bl[2][4];
                #pragma unroll
                for (int mt = 0; mt < 4; mt++) {
                    LDSM4(ah[mt], st + R_AH + aOff + mt * (16 * ROWB) + k16 * 32);
                    LDSM4(al[mt], st + R_AL + aOff + mt * (16 * ROWB) + k16 * 32);
                }
                #pragma unroll
                for (int j = 0; j < 2; j++) {
                    LDSM4(bh[j], st + R_BH + bOff + j * (16 * ROWB) + k16 * 32);
                    if (TERMS == 3)
                        LDSM4(bl[j], st + R_BL + bOff + j * (16 * ROWB) + k16 * 32);
                }
                #pragma unroll
                for (int mt = 0; mt < 4; mt++)
                    #pragma unroll
                    for (int nt = 0; nt < 4; nt++) {
                        const int jj = nt >> 1, hh = (nt & 1) * 2;
                        MMA16816(acc[mt][nt], ah[mt], bh[jj][hh], bh[jj][hh + 1]);
                    }
                #pragma unroll
                for (int mt = 0; mt < 4; mt++)
                    #pragma unroll
                    for (int nt = 0; nt < 4; nt++) {
                        const int jj = nt >> 1, hh = (nt & 1) * 2;
                        MMA16816(acc[mt][nt], al[mt], bh[jj][hh], bh[jj][hh + 1]);
                    }
                if (TERMS == 3) {
                    #pragma unroll
                    for (int mt = 0; mt < 4; mt++)
                        #pragma unroll
                        for (int nt = 0; nt < 4; nt++) {
                            const int jj = nt >> 1, hh = (nt & 1) * 2;
                            MMA16816(acc[mt][nt], ah[mt], bl[jj][hh], bl[jj][hh + 1]);
                        }
                }
            }
            cs = (cs == NSTAGE - 1) ? 0 : cs + 1;
        }
    }

    // ---- epilogue ----
    if (MODE == 2) {
        // Vt hi-only: stage [n][m] in smem, coalesced 16B stores
        const int b = rowBase >> 11;
        const int seq0 = rowBase & 2047;
        const int mloc0 = wm * 64 + (lane >> 2);
        const int nloc0 = wn * 32 + (lane & 3) * 2;
        __half* smt = reinterpret_cast<__half*>(smem);
        constexpr int MP = 136;
        __syncthreads();
        #pragma unroll
        for (int mt = 0; mt < 4; mt++)
            #pragma unroll
            for (int nt = 0; nt < 4; nt++)
                #pragma unroll
                for (int h = 0; h < 2; h++) {
                    const int m = mloc0 + mt * 16 + h * 8;
                    const int n = nloc0 + nt * 8;
                    smt[n * MP + m]       = __float2half_rn(acc[mt][nt][h * 2 + 0] * alpha);
                    smt[(n + 1) * MP + m] = __float2half_rn(acc[mt][nt][h * 2 + 1] * alpha);
                }
        __syncthreads();
        #pragma unroll
        for (int i = 0; i < 8; i++) {
            const int g = tid + i * 256;
            const int n = g >> 4, o = g & 15;
            uint4 val = *reinterpret_cast<const uint4*>(smt + n * MP + o * 8);
            *reinterpret_cast<uint4*>(Ch
                + ((long long)(b * 1024 + colBase + n)) * 2048 + seq0 + o * 8) = val;
        }
    } else {
        const int mBase = rowBase + wm * 64 + (lane >> 2);
        const int nBaseW = colBase + wn * 32 + (lane & 3) * 2;
        #pragma unroll
        for (int mt = 0; mt < 4; mt++)
            #pragma unroll
            for (int nt = 0; nt < 4; nt++) {
                const int n = nBaseW + nt * 8;
                #pragma unroll
                for (int h = 0; h < 2; h++) {
                    const int m = mBase + mt * 16 + h * 8;
                    float v0 = acc[mt][nt][h * 2 + 0] * alpha;
                    float v1 = acc[mt][nt][h * 2 + 1] * alpha;
                    if (MODE == 0) {
                        if (HASBIAS) { v0 += bias[n]; v1 += bias[n + 1]; }
                        float2 w; w.x = v0; w.y = v1;
                        *reinterpret_cast<float2*>(Cf + (long long)blockIdx.z * cOffZ
                            + (long long)m * ldC + n) = w;
                    } else {
                        const long long base = (long long)blockIdx.z * cOffZ
                            + (long long)m * ldC + n;
                        __half h0 = __float2half_rn(v0), h1 = __float2half_rn(v1);
                        __half2 hp; hp.x = h0; hp.y = h1;
                        *reinterpret_cast<__half2*>(Ch + base) = hp;
                        if (MODE == 1) {
                            __half2 lp;
                            lp.x = __float2half_rn(v0 - __half2float(h0));
                            lp.y = __float2half_rn(v1 - __half2float(h1));
                            *reinterpret_cast<__half2*>(Cl + base) = lp;
                        }
                    }
                }
            }
    }
}

// ---- fp32 -> fp16 hi/lo split ----
__global__ __launch_bounds__(256)
void split_kernel(const float4* __restrict__ in, __half2* __restrict__ hi,
                  __half2* __restrict__ lo, int n4)
{
    int i = blockIdx.x * blockDim.x + threadIdx.x;
    if (i >= n4) return;
    float4 v = in[i];
    __half hx = __float2half_rn(v.x), hy = __float2half_rn(v.y);
    __half hz = __float2half_rn(v.z), hw = __float2half_rn(v.w);
    __half2 a, b, c, d;
    a.x = hx; a.y = hy; b.x = hz; b.y = hw;
    c.x = __float2half_rn(v.x - __half2float(hx));
    c.y = __float2half_rn(v.y - __half2float(hy));
    d.x = __float2half_rn(v.z - __half2float(hz));
    d.y = __float2half_rn(v.w - __half2float(hw));
    hi[(size_t)i*2] = a; hi[(size_t)i*2+1] = b;
    lo[(size_t)i*2] = c; lo[(size_t)i*2+1] = d;
}

// ---- all four W[1024][1024] -> Wt hi/lo (transpose + split), z selects ----
__global__ __launch_bounds__(256)
void transpose_split4(const float* __restrict__ w0, const float* __restrict__ w1,
                      const float* __restrict__ w2, const float* __restrict__ w3,
                      __half* __restrict__ Th, __half* __restrict__ Tl)
{
    const float* W = blockIdx.z == 0 ? w0 : blockIdx.z == 1 ? w1 : blockIdx.z == 2 ? w2 : w3;
    __half* oh = Th + (size_t)blockIdx.z * DIM * DIM;
    __half* ol = Tl + (size_t)blockIdx.z * DIM * DIM;
    __shared__ float t[32][33];
    int x = blockIdx.x * 32 + threadIdx.x;
    int y0 = blockIdx.y * 32;
    #pragma unroll
    for (int j = threadIdx.y; j < 32; j += 8)
        t[j][threadIdx.x] = W[(long long)(y0 + j) * DIM + x];
    __syncthreads();
    int xo = y0 + threadIdx.x, yo = blockIdx.x * 32;
    #pragma unroll
    for (int j = threadIdx.y; j < 32; j += 8) {
        float v = t[threadIdx.x][j];
        __half h = __float2half_rn(v);
        long long idx = (long long)(yo + j) * DIM + xo;
        oh[idx] = h;
        ol[idx] = __float2half_rn(v - __half2float(h));
    }
}

// ---- softmax over 2048 cols + fp16 hi/lo split of P ----
__global__ __launch_bounds__(256)
void softmax_split_kernel(const float* __restrict__ S,
                          __half* __restrict__ Ph, __half* __restrict__ Pl)
{
    const float* row = S + (long long)blockIdx.x * SEQ;
    const int tid = threadIdx.x;
    float v[8], m = -CUDART_INF_F;
    #pragma unroll
    for (int i = 0; i < 8; i++) { v[i] = row[tid + i*256]; m = fmaxf(m, v[i]); }
    __shared__ float red[256];
    red[tid] = m; __syncthreads();
    #pragma unroll
    for (int s = 128; s > 0; s >>= 1) { if (tid < s) red[tid] = fmaxf(red[tid], red[tid+s]); __syncthreads(); }
    m = red[0]; __syncthreads();
    float sum = 0.f;
    #pragma unroll
    for (int i = 0; i < 8; i++) { v[i] = __expf(v[i] - m); sum += v[i]; }
    red[tid] = sum; __syncthreads();
    #pragma unroll
    for (int s = 128; s > 0; s >>= 1) { if (tid < s) red[tid] += red[tid+s]; __syncthreads(); }
    float inv = 1.0f / red[0];
    const long long base = (long long)blockIdx.x * SEQ;
    #pragma unroll
    for (int i = 0; i < 8; i++) {
        float p = v[i] * inv;
        __half h = __float2half_rn(p);
        Ph[base + tid + i*256] = h;
        Pl[base + tid + i*256] = __float2half_rn(p - __half2float(h));
    }
}

// ---- launch ----
extern "C" void kernel_launch(void* const* d_in, const int* in_sizes, int n_in,
                              void* d_out, int out_size)
{
    const float* X  = (const float*)d_in[0];
    const float* bo = (const float*)d_in[5];
    float* out = (float*)d_out;

    __half *Xhi, *Xlo, *Qhi, *Qlo, *Khi, *Vthi, *Phi, *Plo, *Ohi, *Olo, *Wth, *Wtl;
    float* Sc;
    cudaGetSymbolAddress((void**)&Xhi, g_Xhi);   cudaGetSymbolAddress((void**)&Xlo, g_Xlo);
    cudaGetSymbolAddress((void**)&Wth, g_Wth);   cudaGetSymbolAddress((void**)&Wtl, g_Wtl);
    cudaGetSymbolAddress((void**)&Qhi, g_Qhi);   cudaGetSymbolAddress((void**)&Qlo, g_Qlo);
    cudaGetSymbolAddress((void**)&Khi, g_Khi);
    cudaGetSymbolAddress((void**)&Vthi, g_Vthi);
    cudaGetSymbolAddress((void**)&Sc, g_S);
    cudaGetSymbolAddress((void**)&Phi, g_Phi);   cudaGetSymbolAddress((void**)&Plo, g_Plo);
    cudaGetSymbolAddress((void**)&Ohi, g_Ohi);   cudaGetSymbolAddress((void**)&Olo, g_Olo);

    cudaFuncSetAttribute(gemm_mma<1,3,false>, cudaFuncAttributeMaxDynamicSharedMemorySize, GEMM_SMEM);
    cudaFuncSetAttribute(gemm_mma<3,3,false>, cudaFuncAttributeMaxDynamicSharedMemorySize, GEMM_SMEM);
    cudaFuncSetAttribute(gemm_mma<2,3,false>, cudaFuncAttributeMaxDynamicSharedMemorySize, GEMM_SMEM);
    cudaFuncSetAttribute(gemm_mma<0,2,false>, cudaFuncAttributeMaxDynamicSharedMemorySize, GEMM_SMEM);
    cudaFuncSetAttribute(gemm_mma<1,2,false>, cudaFuncAttributeMaxDynamicSharedMemorySize, GEMM_SMEM);
    cudaFuncSetAttribute(gemm_mma<0,3,true >, cudaFuncAttributeMaxDynamicSharedMemorySize, GEMM_SMEM);

    const size_t wsz = (size_t)DIM * DIM;

    // 1: X split   2: W transpose+split
    split_kernel<<<(MTOT*DIM/4 + 255)/256, 256>>>((const float4*)X,
        (__half2*)Xhi, (__half2*)Xlo, MTOT*DIM/4);
    transpose_split4<<<dim3(32,32,4), dim3(32,8)>>>((const float*)d_in[1], (const float*)d_in[2],
        (const float*)d_in[3], (const float*)d_in[4], Wth, Wtl);

    // 3-5: Q (hi+lo), K (hi only), Vt (hi only) projections — fp16x3
    {
        dim3 g(DIM/128, MTOT/128, 1);
        gemm_mma<1,3,false><<<g, 256, GEMM_SMEM>>>(Xhi, Xlo, Wth + 0*wsz, Wtl + 0*wsz,
            nullptr, Qhi, Qlo, nullptr, DIM, DIM, 1.0f, 0, 0, 0);
        gemm_mma<3,3,false><<<g, 256, GEMM_SMEM>>>(Xhi, Xlo, Wth + 1*wsz, Wtl + 1*wsz,
            nullptr, Khi, nullptr, nullptr, DIM, DIM, 1.0f, 0, 0, 0);
        gemm_mma<2,3,false><<<g, 256, GEMM_SMEM>>>(Xhi, Xlo, Wth + 2*wsz, Wtl + 2*wsz,
            nullptr, Vthi, nullptr, nullptr, DIM, DIM, 1.0f, 0, 0, 0);
    }

    // 6: scores = (Q @ K^T)/32 — 2-term (A=Q corrected, B=Khi)
    {
        dim3 g(SEQ/128, SEQ/128, BATCH);
        gemm_mma<0,2,false><<<g, 256, GEMM_SMEM>>>(Qhi, Qlo, Khi, nullptr,
            Sc, nullptr, nullptr, nullptr, DIM, SEQ, 1.0f/32.0f,
            (long long)SEQ, (long long)SEQ, (long long)SEQ * SEQ);
    }

    // 7: softmax + fp16 split -> P hi/lo
    softmax_split_kernel<<<BATCH*SEQ, 256>>>(Sc, Phi, Plo);

    // 8: O = P @ V — 2-term (A=P corrected, B=Vt hi), hi+lo out
    {
        dim3 g(DIM/128, SEQ/128, BATCH);
        gemm_mma<1,2,false><<<g, 256, GEMM_SMEM>>>(Phi, Plo, Vthi, nullptr,
            nullptr, Ohi, Olo, nullptr, SEQ, DIM, 1.0f,
            (long long)SEQ, (long long)DIM, (long long)SEQ * DIM);
    }

    // 9: out = O @ Wo + bo — fp16x3
    {
        dim3 g(DIM/128, MTOT/128, 1);
        gemm_mma<0,3,true><<<g, 256, GEMM_SMEM>>>(Ohi, Olo, Wth + 3*wsz, Wtl + 3*wsz,
            out, nullptr, nullptr, bo, DIM, DIM, 1.0f, 0, 0, 0);
    }
}

// round 14
// speedup vs baseline: 1.3963x; 1.1959x over previous
#include <cuda_runtime.h>
#include <cuda_fp16.h>
#include <cstdint>
#include <math_constants.h>

constexpr int BATCH = 4, SEQ = 2048, DIM = 1024, MTOT = BATCH * SEQ;

// ---- scratch (device globals; 16B-aligned) ----
__device__ __align__(16) __half g_Xhi [(size_t)MTOT * DIM];
__device__ __align__(16) __half g_Xlo [(size_t)MTOT * DIM];
__device__ __align__(16) __half g_Wth [4][(size_t)DIM * DIM];
__device__ __align__(16) __half g_Wtl [4][(size_t)DIM * DIM];
__device__ __align__(16) __half g_Qhi [(size_t)MTOT * DIM];
__device__ __align__(16) __half g_Qlo [(size_t)MTOT * DIM];
__device__ __align__(16) __half g_Khi [(size_t)MTOT * DIM];
__device__ __align__(16) __half g_Vthi[(size_t)BATCH * DIM * SEQ];
__device__ __align__(16) float  g_S   [(size_t)BATCH * SEQ * SEQ];
__device__ __align__(16) __half g_Phi [(size_t)BATCH * SEQ * SEQ];
__device__ __align__(16) __half g_Plo [(size_t)BATCH * SEQ * SEQ];
__device__ __align__(16) __half g_Ohi [(size_t)MTOT * DIM];
__device__ __align__(16) __half g_Olo [(size_t)MTOT * DIM];

__device__ __forceinline__ uint32_t s2u(const void* p) {
    uint32_t a;
    asm("{ .reg .u64 t; cvta.to.shared.u64 t, %1; cvt.u32.u64 %0, t; }" : "=r"(a) : "l"(p));
    return a;
}
#define CPA16(dst, src) \
    asm volatile("cp.async.cg.shared.global [%0], [%1], 16;" :: "r"(dst), "l"(src) : "memory")
#define LDSM4(r, a) \
    asm volatile("ldmatrix.sync.aligned.m8n8.x4.shared.b16 {%0,%1,%2,%3}, [%4];" \
        : "=r"((r)[0]), "=r"((r)[1]), "=r"((r)[2]), "=r"((r)[3]) : "r"(a))
#define MMA16816(c, a, b0, b1) \
    asm volatile("mma.sync.aligned.m16n8k16.row.col.f32.f16.f16.f32 " \
        "{%0,%1,%2,%3}, {%4,%5,%6,%7}, {%8,%9}, {%0,%1,%2,%3};" \
        : "+f"((c)[0]), "+f"((c)[1]), "+f"((c)[2]), "+f"((c)[3]) \
        : "r"((a)[0]), "r"((a)[1]), "r"((a)[2]), "r"((a)[3]), "r"(b0), "r"(b1))

// ---- GEMM: D[m][n] = sum_k A[m][k]*B[n][k]; fp16 split via mma.sync ----
// TERMS=3: AhBh + AhBl + AlBh (err ~2^-23). TERMS=2: AhBh + AlBh (B err ~2^-12).
// CTA 128x128, 8 warps (2x4), warp tile 64x32, K-chunk 32, 5-stage cp.async,
// one __syncthreads per 64 K (two stages per barrier). ROWB=80 conflict-free.
constexpr int ROWB = 80;
constexpr int R_AH = 0, R_AL = 10240, R_BH = 20480, R_BL = 30720;
constexpr int STAGE_SZ = 40960;
constexpr int NSTAGE = 5;
constexpr int GEMM_SMEM = NSTAGE * STAGE_SZ;      // 204800

// MODE 0: fp32 out (alpha, opt bias). MODE 1: hi+lo out. MODE 2: Vt hi-only out.
// MODE 3: hi-only out.
template<int MODE, int TERMS, bool HASBIAS>
__global__ __launch_bounds__(256, 1)
void gemm_mma(const __half* __restrict__ Ah, const __half* __restrict__ Al,
              const __half* __restrict__ Bh, const __half* __restrict__ Bl,
              float* __restrict__ Cf,
              __half* __restrict__ Ch, __half* __restrict__ Cl,
              const float* __restrict__ bias,
              int Kd, int ldC, float alpha,
              long long aRowZ, long long bRowZ, long long cOffZ)
{
    extern __shared__ __align__(128) char smem[];
    const uint32_t sb = s2u(smem);
    const int tid = threadIdx.x, wid = tid >> 5, lane = tid & 31;
    const int wm = wid >> 2, wn = wid & 3;
    const int rowBase = blockIdx.y * 128, colBase = blockIdx.x * 128;
    const long long aRow0 = (long long)blockIdx.z * aRowZ + rowBase;
    const long long bRow0 = (long long)blockIdx.z * bRowZ + colBase;

    const int r = tid >> 2, cg = tid & 3;
    const long long rowStep = (long long)Kd * 2;
    const char* pAH = (const char*)Ah + (aRow0 + r) * rowStep + cg * 16;
    const char* pAL = (const char*)Al + (aRow0 + r) * rowStep + cg * 16;
    const char* pBH = (const char*)Bh + (bRow0 + r) * rowStep + cg * 16;
    const char* pBL = (TERMS == 3) ? (const char*)Bl + (bRow0 + r) * rowStep + cg * 16 : nullptr;
    const uint32_t dRow = (uint32_t)(r * ROWB + cg * 16);
    const long long rowStep64 = 64 * rowStep;
    const int nCh = Kd >> 5;

    auto load_stage = [&](int c, int s) {
        const uint32_t d = sb + s * STAGE_SZ + dRow;
        const long long cb = (long long)c * 64;
        #pragma unroll
        for (int i = 0; i < 2; i++) {
            CPA16(d + R_AH + i * 64 * ROWB, pAH + i * rowStep64 + cb);
            CPA16(d + R_AL + i * 64 * ROWB, pAL + i * rowStep64 + cb);
            CPA16(d + R_BH + i * 64 * ROWB, pBH + i * rowStep64 + cb);
            if (TERMS == 3)
                CPA16(d + R_BL + i * 64 * ROWB, pBL + i * rowStep64 + cb);
        }
        asm volatile("cp.async.commit_group;" ::: "memory");
    };

    const uint32_t aOff = (uint32_t)((wm * 64 + (lane & 7) + ((lane >> 3) & 1) * 8) * ROWB
                                     + ((lane >> 4) * 8) * 2);
    const uint32_t bOff = (uint32_t)((wn * 32 + (lane & 7) + ((lane >> 4) & 1) * 8) * ROWB
                                     + (((lane >> 3) & 1) * 8) * 2);

    float acc[4][4][4];
    #pragma unroll
    for (int i = 0; i < 4; i++)
        #pragma unroll
        for (int j = 0; j < 4; j++)
            #pragma unroll
            for (int q = 0; q < 4; q++) acc[i][j][q] = 0.0f;

    load_stage(0, 0);
    load_stage(1, 1);
    load_stage(2, 2);

    int nc = 3, ps = 3;
    int cs = 0;

    for (int cc = 0; cc < nCh; cc += 2) {
        if (cc + 2 < nCh) asm volatile("cp.async.wait_group 1;" ::: "memory");
        else              asm volatile("cp.async.wait_group 0;" ::: "memory");
        __syncthreads();
        #pragma unroll
        for (int j = 0; j < 2; j++) {
            if (nc < nCh) {
                load_stage(nc, ps);
                nc++;
                ps = (ps == NSTAGE - 1) ? 0 : ps + 1;
            }
        }

        #pragma unroll
        for (int half = 0; half < 2; half++) {
            const uint32_t st = sb + cs * STAGE_SZ;
            #pragma unroll
            for (int k16 = 0; k16 < 2; k16++) {
                uint32_t ah[4][4], al[4][4], bh[2][4], bl[2][4];
                #pragma unroll
                for (int mt = 0; mt < 4; mt++) {
                    LDSM4(ah[mt], st + R_AH + aOff + mt * (16 * ROWB) + k16 * 32);
                    LDSM4(al[mt], st + R_AL + aOff + mt * (16 * ROWB) + k16 * 32);
                }
                #pragma unroll
                for (int j = 0; j < 2; j++) {
                    LDSM4(bh[j], st + R_BH + bOff + j * (16 * ROWB) + k16 * 32);
                    if (TERMS == 3)
                        LDSM4(bl[j], st + R_BL + bOff + j * (16 * ROWB) + k16 * 32);
                }
                #pragma unroll
                for (int mt = 0; mt < 4; mt++)
                    #pragma unroll
                    for (int nt = 0; nt < 4; nt++) {
                        const int jj = nt >> 1, hh = (nt & 1) * 2;
                        MMA16816(acc[mt][nt], ah[mt], bh[jj][hh], bh[jj][hh + 1]);
                    }
                #pragma unroll
                for (int mt = 0; mt < 4; mt++)
                    #pragma unroll
                    for (int nt = 0; nt < 4; nt++) {
                        const int jj = nt >> 1, hh = (nt & 1) * 2;
                        MMA16816(acc[mt][nt], al[mt], bh[jj][hh], bh[jj][hh + 1]);
                    }
                if (TERMS == 3) {
                    #pragma unroll
                    for (int mt = 0; mt < 4; mt++)
                        #pragma unroll
                        for (int nt = 0; nt < 4; nt++) {
                            const int jj = nt >> 1, hh = (nt & 1) * 2;
                            MMA16816(acc[mt][nt], ah[mt], bl[jj][hh], bl[jj][hh + 1]);
                        }
                }
            }
            cs = (cs == NSTAGE - 1) ? 0 : cs + 1;
        }
    }

    // ---- epilogue ----
    if (MODE == 2) {
        // Vt hi-only: stage [n][m] in smem, coalesced 16B stores
        const int b = rowBase >> 11;
        const int seq0 = rowBase & 2047;
        const int mloc0 = wm * 64 + (lane >> 2);
        const int nloc0 = wn * 32 + (lane & 3) * 2;
        __half* smt = reinterpret_cast<__half*>(smem);
        constexpr int MP = 136;
        __syncthreads();
        #pragma unroll
        for (int mt = 0; mt < 4; mt++)
            #pragma unroll
            for (int nt = 0; nt < 4; nt++)
                #pragma unroll
                for (int h = 0; h < 2; h++) {
                    const int m = mloc0 + mt * 16 + h * 8;
                    const int n = nloc0 + nt * 8;
                    smt[n * MP + m]       = __float2half_rn(acc[mt][nt][h * 2 + 0] * alpha);
                    smt[(n + 1) * MP + m] = __float2half_rn(acc[mt][nt][h * 2 + 1] * alpha);
                }
        __syncthreads();
        #pragma unroll
        for (int i = 0; i < 8; i++) {
            const int g = tid + i * 256;
            const int n = g >> 4, o = g & 15;
            uint4 val = *reinterpret_cast<const uint4*>(smt + n * MP + o * 8);
            *reinterpret_cast<uint4*>(Ch
                + ((long long)(b * 1024 + colBase + n)) * 2048 + seq0 + o * 8) = val;
        }
    } else {
        const int mBase = rowBase + wm * 64 + (lane >> 2);
        const int nBaseW = colBase + wn * 32 + (lane & 3) * 2;
        #pragma unroll
        for (int mt = 0; mt < 4; mt++)
            #pragma unroll
            for (int nt = 0; nt < 4; nt++) {
                const int n = nBaseW + nt * 8;
                #pragma unroll
                for (int h = 0; h < 2; h++) {
                    const int m = mBase + mt * 16 + h * 8;
                    float v0 = acc[mt][nt][h * 2 + 0] * alpha;
                    float v1 = acc[mt][nt][h * 2 + 1] * alpha;
                    if (MODE == 0) {
                        if (HASBIAS) { v0 += bias[n]; v1 += bias[n + 1]; }
                        float2 w; w.x = v0; w.y = v1;
                        *reinterpret_cast<float2*>(Cf + (long long)blockIdx.z * cOffZ
                            + (long long)m * ldC + n) = w;
                    } else {
                        const long long base = (long long)blockIdx.z * cOffZ
                            + (long long)m * ldC + n;
                        __half h0 = __float2half_rn(v0), h1 = __float2half_rn(v1);
                        __half2 hp; hp.x = h0; hp.y = h1;
                        *reinterpret_cast<__half2*>(Ch + base) = hp;
                        if (MODE == 1) {
                            __half2 lp;
                            lp.x = __float2half_rn(v0 - __half2float(h0));
                            lp.y = __float2half_rn(v1 - __half2float(h1));
                            *reinterpret_cast<__half2*>(Cl + base) = lp;
                        }
                    }
                }
            }
    }
}

// ---- fp32 -> fp16 hi/lo split ----
__global__ __launch_bounds__(256)
void split_kernel(const float4* __restrict__ in, __half2* __restrict__ hi,
                  __half2* __restrict__ lo, int n4)
{
    int i = blockIdx.x * blockDim.x + threadIdx.x;
    if (i >= n4) return;
    float4 v = in[i];
    __half hx = __float2half_rn(v.x), hy = __float2half_rn(v.y);
    __half hz = __float2half_rn(v.z), hw = __float2half_rn(v.w);
    __half2 a, b, c, d;
    a.x = hx; a.y = hy; b.x = hz; b.y = hw;
    c.x = __float2half_rn(v.x - __half2float(hx));
    c.y = __float2half_rn(v.y - __half2float(hy));
    d.x = __float2half_rn(v.z - __half2float(hz));
    d.y = __float2half_rn(v.w - __half2float(hw));
    hi[(size_t)i*2] = a; hi[(size_t)i*2+1] = b;
    lo[(size_t)i*2] = c; lo[(size_t)i*2+1] = d;
}

// ---- all four W[1024][1024] -> Wt hi/lo (transpose + split), z selects ----
__global__ __launch_bounds__(256)
void transpose_split4(const float* __restrict__ w0, const float* __restrict__ w1,
                      const float* __restrict__ w2, const float* __restrict__ w3,
                      __half* __restrict__ Th, __half* __restrict__ Tl)
{
    const float* W = blockIdx.z == 0 ? w0 : blockIdx.z == 1 ? w1 : blockIdx.z == 2 ? w2 : w3;
    __half* oh = Th + (size_t)blockIdx.z * DIM * DIM;
    __half* ol = Tl + (size_t)blockIdx.z * DIM * DIM;
    __shared__ float t[32][33];
    int x = blockIdx.x * 32 + threadIdx.x;
    int y0 = blockIdx.y * 32;
    #pragma unroll
    for (int j = threadIdx.y; j < 32; j += 8)
        t[j][threadIdx.x] = W[(long long)(y0 + j) * DIM + x];
    __syncthreads();
    int xo = y0 + threadIdx.x, yo = blockIdx.x * 32;
    #pragma unroll
    for (int j = threadIdx.y; j < 32; j += 8) {
        float v = t[threadIdx.x][j];
        __half h = __float2half_rn(v);
        long long idx = (long long)(yo + j) * DIM + xo;
        oh[idx] = h;
        ol[idx] = __float2half_rn(v - __half2float(h));
    }
}

// ---- softmax over 2048 cols + fp16 hi/lo split of P ----
__global__ __launch_bounds__(256)
void softmax_split_kernel(const float* __restrict__ S,
                          __half* __restrict__ Ph, __half* __restrict__ Pl)
{
    const float* row = S + (long long)blockIdx.x * SEQ;
    const int tid = threadIdx.x;
    float v[8], m = -CUDART_INF_F;
    #pragma unroll
    for (int i = 0; i < 8; i++) { v[i] = row[tid + i*256]; m = fmaxf(m, v[i]); }
    __shared__ float red[256];
    red[tid] = m; __syncthreads();
    #pragma unroll
    for (int s = 128; s > 0; s >>= 1) { if (tid < s) red[tid] = fmaxf(red[tid], red[tid+s]); __syncthreads(); }
    m = red[0]; __syncthreads();
    float sum = 0.f;
    #pragma unroll
    for (int i = 0; i < 8; i++) { v[i] = __expf(v[i] - m); sum += v[i]; }
    red[tid] = sum; __syncthreads();
    #pragma unroll
    for (int s = 128; s > 0; s >>= 1) { if (tid < s) red[tid] += red[tid+s]; __syncthreads(); }
    float inv = 1.0f / red[0];
    const long long base = (long long)blockIdx.x * SEQ;
    #pragma unroll
    for (int i = 0; i < 8; i++) {
        float p = v[i] * inv;
        __half h = __float2half_rn(p);
        Ph[base + tid + i*256] = h;
        Pl[base + tid + i*256] = __float2half_rn(p - __half2float(h));
    }
}

// ---- launch ----
extern "C" void kernel_launch(void* const* d_in, const int* in_sizes, int n_in,
                              void* d_out, int out_size)
{
    const float* X  = (const float*)d_in[0];
    const float* bo = (const float*)d_in[5];
    float* out = (float*)d_out;

    __half *Xhi, *Xlo, *Qhi, *Qlo, *Khi, *Vthi, *Phi, *Plo, *Ohi, *Olo, *Wth, *Wtl;
    float* Sc;
    cudaGetSymbolAddress((void**)&Xhi, g_Xhi);   cudaGetSymbolAddress((void**)&Xlo, g_Xlo);
    cudaGetSymbolAddress((void**)&Wth, g_Wth);   cudaGetSymbolAddress((void**)&Wtl, g_Wtl);
    cudaGetSymbolAddress((void**)&Qhi, g_Qhi);   cudaGetSymbolAddress((void**)&Qlo, g_Qlo);
    cudaGetSymbolAddress((void**)&Khi, g_Khi);
    cudaGetSymbolAddress((void**)&Vthi, g_Vthi);
    cudaGetSymbolAddress((void**)&Sc, g_S);
    cudaGetSymbolAddress((void**)&Phi, g_Phi);   cudaGetSymbolAddress((void**)&Plo, g_Plo);
    cudaGetSymbolAddress((void**)&Ohi, g_Ohi);   cudaGetSymbolAddress((void**)&Olo, g_Olo);

    cudaFuncSetAttribute(gemm_mma<1,2,false>, cudaFuncAttributeMaxDynamicSharedMemorySize, GEMM_SMEM);
    cudaFuncSetAttribute(gemm_mma<3,2,false>, cudaFuncAttributeMaxDynamicSharedMemorySize, GEMM_SMEM);
    cudaFuncSetAttribute(gemm_mma<2,2,false>, cudaFuncAttributeMaxDynamicSharedMemorySize, GEMM_SMEM);
    cudaFuncSetAttribute(gemm_mma<0,2,false>, cudaFuncAttributeMaxDynamicSharedMemorySize, GEMM_SMEM);
    cudaFuncSetAttribute(gemm_mma<0,2,true >, cudaFuncAttributeMaxDynamicSharedMemorySize, GEMM_SMEM);

    const size_t wsz = (size_t)DIM * DIM;

    // 1: X split   2: W transpose+split
    split_kernel<<<(MTOT*DIM/4 + 255)/256, 256>>>((const float4*)X,
        (__half2*)Xhi, (__half2*)Xlo, MTOT*DIM/4);
    transpose_split4<<<dim3(32,32,4), dim3(32,8)>>>((const float*)d_in[1], (const float*)d_in[2],
        (const float*)d_in[3], (const float*)d_in[4], Wth, Wtl);

    // 3-5: Q (hi+lo), K (hi only), Vt (hi only) projections — 2-term (A=X corrected)
    {
        dim3 g(DIM/128, MTOT/128, 1);
        gemm_mma<1,2,false><<<g, 256, GEMM_SMEM>>>(Xhi, Xlo, Wth + 0*wsz, nullptr,
            nullptr, Qhi, Qlo, nullptr, DIM, DIM, 1.0f, 0, 0, 0);
        gemm_mma<3,2,false><<<g, 256, GEMM_SMEM>>>(Xhi, Xlo, Wth + 1*wsz, nullptr,
            nullptr, Khi, nullptr, nullptr, DIM, DIM, 1.0f, 0, 0, 0);
        gemm_mma<2,2,false><<<g, 256, GEMM_SMEM>>>(Xhi, Xlo, Wth + 2*wsz, nullptr,
            nullptr, Vthi, nullptr, nullptr, DIM, DIM, 1.0f, 0, 0, 0);
    }

    // 6: scores = (Q @ K^T)/32 — 2-term (A=Q corrected, B=Khi)
    {
        dim3 g(SEQ/128, SEQ/128, BATCH);
        gemm_mma<0,2,false><<<g, 256, GEMM_SMEM>>>(Qhi, Qlo, Khi, nullptr,
            Sc, nullptr, nullptr, nullptr, DIM, SEQ, 1.0f/32.0f,
            (long long)SEQ, (long long)SEQ, (long long)SEQ * SEQ);
    }

    // 7: softmax + fp16 split -> P hi/lo
    softmax_split_kernel<<<BATCH*SEQ, 256>>>(Sc, Phi, Plo);

    // 8: O = P @ V — 2-term (A=P corrected, B=Vt hi), hi+lo out
    {
        dim3 g(DIM/128, SEQ/128, BATCH);
        gemm_mma<1,2,false><<<g, 256, GEMM_SMEM>>>(Phi, Plo, Vthi, nullptr,
            nullptr, Ohi, Olo, nullptr, SEQ, DIM, 1.0f,
            (long long)SEQ, (long long)DIM, (long long)SEQ * DIM);
    }

    // 9: out = O @ Wo + bo — 2-term (A=O corrected, B=Wo hi)
    {
        dim3 g(DIM/128, MTOT/128, 1);
        gemm_mma<0,2,true><<<g, 256, GEMM_SMEM>>>(Ohi, Olo, Wth + 3*wsz, nullptr,
            out, nullptr, nullptr, bo, DIM, DIM, 1.0f, 0, 0, 0);
    }
}

// round 15
// speedup vs baseline: 1.5670x; 1.1222x over previous
#include <cuda_runtime.h>
#include <cuda_fp16.h>
#include <cstdint>
#include <math_constants.h>

constexpr int BATCH = 4, SEQ = 2048, DIM = 1024, MTOT = BATCH * SEQ;

// ---- scratch (device globals; 16B-aligned) ----
__device__ __align__(16) __half g_Xhi [(size_t)MTOT * DIM];
__device__ __align__(16) __half g_Xlo [(size_t)MTOT * DIM];
__device__ __align__(16) __half g_Wth [4][(size_t)DIM * DIM];
__device__ __align__(16) __half g_Qhi [(size_t)MTOT * DIM];
__device__ __align__(16) __half g_Qlo [(size_t)MTOT * DIM];
__device__ __align__(16) __half g_Khi [(size_t)MTOT * DIM];
__device__ __align__(16) __half g_Vthi[(size_t)BATCH * DIM * SEQ];
__device__ __align__(16) float  g_S   [(size_t)BATCH * SEQ * SEQ];
__device__ __align__(16) __half g_Phi [(size_t)BATCH * SEQ * SEQ];
__device__ __align__(16) __half g_Plo [(size_t)BATCH * SEQ * SEQ];
__device__ __align__(16) __half g_Ohi [(size_t)MTOT * DIM];
__device__ __align__(16) __half g_Olo [(size_t)MTOT * DIM];

__device__ __forceinline__ uint32_t s2u(const void* p) {
    uint32_t a;
    asm("{ .reg .u64 t; cvta.to.shared.u64 t, %1; cvt.u32.u64 %0, t; }" : "=r"(a) : "l"(p));
    return a;
}
#define CPA16(dst, src) \
    asm volatile("cp.async.cg.shared.global [%0], [%1], 16;" :: "r"(dst), "l"(src) : "memory")
#define LDSM4(r, a) \
    asm volatile("ldmatrix.sync.aligned.m8n8.x4.shared.b16 {%0,%1,%2,%3}, [%4];" \
        : "=r"((r)[0]), "=r"((r)[1]), "=r"((r)[2]), "=r"((r)[3]) : "r"(a))
#define MMA16816(c, a, b0, b1) \
    asm volatile("mma.sync.aligned.m16n8k16.row.col.f32.f16.f16.f32 " \
        "{%0,%1,%2,%3}, {%4,%5,%6,%7}, {%8,%9}, {%0,%1,%2,%3};" \
        : "+f"((c)[0]), "+f"((c)[1]), "+f"((c)[2]), "+f"((c)[3]) \
        : "r"((a)[0]), "r"((a)[1]), "r"((a)[2]), "r"((a)[3]), "r"(b0), "r"(b1))

// ---- GEMM: D[m][n] = sum_k A[m][k]*B[n][k]; fp16 2-term (AhBh + AlBh) ----
// CTA 128x256, 8 warps (2x4), warp tile 64x64, K-chunk 32, 5-stage cp.async,
// one __syncthreads per 64 K (two stages per barrier). ROWB=80 conflict-free.
constexpr int ROWB = 80;
constexpr int R_AH = 0, R_AL = 10240, R_BH = 20480;
constexpr int STAGE_SZ = 40960;          // 20480 A(hi+lo) + 20480 B(hi, 256 rows)
constexpr int NSTAGE = 5;
constexpr int GEMM_SMEM = NSTAGE * STAGE_SZ;      // 204800

// MODE 0: fp32 out (alpha, opt bias). MODE 1: hi+lo out. MODE 2: Vt hi-only out.
// MODE 3: hi-only out.
template<int MODE, bool HASBIAS>
__global__ __launch_bounds__(256, 1)
void gemm_mma(const __half* __restrict__ Ah, const __half* __restrict__ Al,
              const __half* __restrict__ Bh,
              float* __restrict__ Cf,
              __half* __restrict__ Ch, __half* __restrict__ Cl,
              const float* __restrict__ bias,
              int Kd, int ldC, float alpha,
              long long aRowZ, long long bRowZ, long long cOffZ)
{
    extern __shared__ __align__(128) char smem[];
    const uint32_t sb = s2u(smem);
    const int tid = threadIdx.x, wid = tid >> 5, lane = tid & 31;
    const int wm = wid >> 2, wn = wid & 3;
    const int rowBase = blockIdx.y * 128, colBase = blockIdx.x * 256;
    const long long aRow0 = (long long)blockIdx.z * aRowZ + rowBase;
    const long long bRow0 = (long long)blockIdx.z * bRowZ + colBase;

    // cp.async geometry: thread -> (row r=tid/4 in 0..63, granule cg=tid&3)
    const int r = tid >> 2, cg = tid & 3;
    const long long rowStep = (long long)Kd * 2;
    const char* pAH = (const char*)Ah + (aRow0 + r) * rowStep + cg * 16;
    const char* pAL = (const char*)Al + (aRow0 + r) * rowStep + cg * 16;
    const char* pBH = (const char*)Bh + (bRow0 + r) * rowStep + cg * 16;
    const uint32_t dRow = (uint32_t)(r * ROWB + cg * 16);
    const long long rowStep64 = 64 * rowStep;
    const int nCh = Kd >> 5;

    auto load_stage = [&](int c, int s) {
        const uint32_t d = sb + s * STAGE_SZ + dRow;
        const long long cb = (long long)c * 64;
        CPA16(d + R_AH,             pAH + cb);
        CPA16(d + R_AH + 64 * ROWB, pAH + rowStep64 + cb);
        CPA16(d + R_AL,             pAL + cb);
        CPA16(d + R_AL + 64 * ROWB, pAL + rowStep64 + cb);
        #pragma unroll
        for (int i = 0; i < 4; i++)          // B: 256 rows
            CPA16(d + R_BH + i * 64 * ROWB, pBH + i * rowStep64 + cb);
        asm volatile("cp.async.commit_group;" ::: "memory");
    };

    const uint32_t aOff = (uint32_t)((wm * 64 + (lane & 7) + ((lane >> 3) & 1) * 8) * ROWB
                                     + ((lane >> 4) * 8) * 2);
    const uint32_t bOff = (uint32_t)((wn * 64 + (lane & 7) + ((lane >> 4) & 1) * 8) * ROWB
                                     + (((lane >> 3) & 1) * 8) * 2);

    float acc[4][8][4];
    #pragma unroll
    for (int i = 0; i < 4; i++)
        #pragma unroll
        for (int j = 0; j < 8; j++)
            #pragma unroll
            for (int q = 0; q < 4; q++) acc[i][j][q] = 0.0f;

    load_stage(0, 0);
    load_stage(1, 1);
    load_stage(2, 2);

    int nc = 3, ps = 3;
    int cs = 0;

    for (int cc = 0; cc < nCh; cc += 2) {
        if (cc + 2 < nCh) asm volatile("cp.async.wait_group 1;" ::: "memory");
        else              asm volatile("cp.async.wait_group 0;" ::: "memory");
        __syncthreads();
        #pragma unroll
        for (int j = 0; j < 2; j++) {
            if (nc < nCh) {
                load_stage(nc, ps);
                nc++;
                ps = (ps == NSTAGE - 1) ? 0 : ps + 1;
            }
        }

        #pragma unroll
        for (int half = 0; half < 2; half++) {
            const uint32_t st = sb + cs * STAGE_SZ;
            #pragma unroll
            for (int k16 = 0; k16 < 2; k16++) {
                uint32_t ah[4][4], al[4][4], bh[4][4];
                #pragma unroll
                for (int mt = 0; mt < 4; mt++) {
                    LDSM4(ah[mt], st + R_AH + aOff + mt * (16 * ROWB) + k16 * 32);
                    LDSM4(al[mt], st + R_AL + aOff + mt * (16 * ROWB) + k16 * 32);
                }
                #pragma unroll
                for (int j = 0; j < 4; j++)
                    LDSM4(bh[j], st + R_BH + bOff + j * (16 * ROWB) + k16 * 32);
                #pragma unroll
                for (int mt = 0; mt < 4; mt++)
                    #pragma unroll
                    for (int nt = 0; nt < 8; nt++) {
                        const int jj = nt >> 1, hh = (nt & 1) * 2;
                        MMA16816(acc[mt][nt], ah[mt], bh[jj][hh], bh[jj][hh + 1]);
                    }
                #pragma unroll
                for (int mt = 0; mt < 4; mt++)
                    #pragma unroll
                    for (int nt = 0; nt < 8; nt++) {
                        const int jj = nt >> 1, hh = (nt & 1) * 2;
                        MMA16816(acc[mt][nt], al[mt], bh[jj][hh], bh[jj][hh + 1]);
                    }
            }
            cs = (cs == NSTAGE - 1) ? 0 : cs + 1;
        }
    }

    // ---- epilogue ----
    if (MODE == 2) {
        // Vt hi-only: stage [n][m] (256 x 128) in smem, coalesced 16B stores
        const int b = rowBase >> 11;
        const int seq0 = rowBase & 2047;
        const int mloc0 = wm * 64 + (lane >> 2);
        const int nloc0 = wn * 64 + (lane & 3) * 2;
        __half* smt = reinterpret_cast<__half*>(smem);
        constexpr int MP = 136;
        __syncthreads();
        #pragma unroll
        for (int mt = 0; mt < 4; mt++)
            #pragma unroll
            for (int nt = 0; nt < 8; nt++)
                #pragma unroll
                for (int h = 0; h < 2; h++) {
                    const int m = mloc0 + mt * 16 + h * 8;
                    const int n = nloc0 + nt * 8;
                    smt[n * MP + m]       = __float2half_rn(acc[mt][nt][h * 2 + 0] * alpha);
                    smt[(n + 1) * MP + m] = __float2half_rn(acc[mt][nt][h * 2 + 1] * alpha);
                }
        __syncthreads();
        #pragma unroll
        for (int i = 0; i < 16; i++) {
            const int g = tid + i * 256;          // 0..4095
            const int n = g >> 4, o = g & 15;     // 256 rows x 16 granules
            uint4 val = *reinterpret_cast<const uint4*>(smt + n * MP + o * 8);
            *reinterpret_cast<uint4*>(Ch
                + ((long long)(b * 1024 + colBase + n)) * 2048 + seq0 + o * 8) = val;
        }
    } else {
        const int mBase = rowBase + wm * 64 + (lane >> 2);
        const int nBaseW = colBase + wn * 64 + (lane & 3) * 2;
        #pragma unroll
        for (int mt = 0; mt < 4; mt++)
            #pragma unroll
            for (int nt = 0; nt < 8; nt++) {
                const int n = nBaseW + nt * 8;
                #pragma unroll
                for (int h = 0; h < 2; h++) {
                    const int m = mBase + mt * 16 + h * 8;
                    float v0 = acc[mt][nt][h * 2 + 0] * alpha;
                    float v1 = acc[mt][nt][h * 2 + 1] * alpha;
                    if (MODE == 0) {
                        if (HASBIAS) { v0 += bias[n]; v1 += bias[n + 1]; }
                        float2 w; w.x = v0; w.y = v1;
                        *reinterpret_cast<float2*>(Cf + (long long)blockIdx.z * cOffZ
                            + (long long)m * ldC + n) = w;
                    } else {
                        const long long base = (long long)blockIdx.z * cOffZ
                            + (long long)m * ldC + n;
                        __half h0 = __float2half_rn(v0), h1 = __float2half_rn(v1);
                        __half2 hp; hp.x = h0; hp.y = h1;
                        *reinterpret_cast<__half2*>(Ch + base) = hp;
                        if (MODE == 1) {
                            __half2 lp;
                            lp.x = __float2half_rn(v0 - __half2float(h0));
                            lp.y = __float2half_rn(v1 - __half2float(h1));
                            *reinterpret_cast<__half2*>(Cl + base) = lp;
                        }
                    }
                }
            }
    }
}

// ---- fp32 -> fp16 hi/lo split ----
__global__ __launch_bounds__(256)
void split_kernel(const float4* __restrict__ in, __half2* __restrict__ hi,
                  __half2* __restrict__ lo, int n4)
{
    int i = blockIdx.x * blockDim.x + threadIdx.x;
    if (i >= n4) return;
    float4 v = in[i];
    __half hx = __float2half_rn(v.x), hy = __float2half_rn(v.y);
    __half hz = __float2half_rn(v.z), hw = __float2half_rn(v.w);
    __half2 a, b, c, d;
    a.x = hx; a.y = hy; b.x = hz; b.y = hw;
    c.x = __float2half_rn(v.x - __half2float(hx));
    c.y = __float2half_rn(v.y - __half2float(hy));
    d.x = __float2half_rn(v.z - __half2float(hz));
    d.y = __float2half_rn(v.w - __half2float(hw));
    hi[(size_t)i*2] = a; hi[(size_t)i*2+1] = b;
    lo[(size_t)i*2] = c; lo[(size_t)i*2+1] = d;
}

// ---- all four W[1024][1024] -> Wt hi (transpose), z selects ----
__global__ __launch_bounds__(256)
void transpose_h4(const float* __restrict__ w0, const float* __restrict__ w1,
                  const float* __restrict__ w2, const float* __restrict__ w3,
                  __half* __restrict__ Th)
{
    const float* W = blockIdx.z == 0 ? w0 : blockIdx.z == 1 ? w1 : blockIdx.z == 2 ? w2 : w3;
    __half* oh = Th + (size_t)blockIdx.z * DIM * DIM;
    __shared__ float t[32][33];
    int x = blockIdx.x * 32 + threadIdx.x;
    int y0 = blockIdx.y * 32;
    #pragma unroll
    for (int j = threadIdx.y; j < 32; j += 8)
        t[j][threadIdx.x] = W[(long long)(y0 + j) * DIM + x];
    __syncthreads();
    int xo = y0 + threadIdx.x, yo = blockIdx.x * 32;
    #pragma unroll
    for (int j = threadIdx.y; j < 32; j += 8)
        oh[(long long)(yo + j) * DIM + xo] = __float2half_rn(t[threadIdx.x][j]);
}

// ---- softmax over 2048 cols + fp16 hi/lo split of P ----
__global__ __launch_bounds__(256)
void softmax_split_kernel(const float* __restrict__ S,
                          __half* __restrict__ Ph, __half* __restrict__ Pl)
{
    const float* row = S + (long long)blockIdx.x * SEQ;
    const int tid = threadIdx.x;
    float v[8], m = -CUDART_INF_F;
    #pragma unroll
    for (int i = 0; i < 8; i++) { v[i] = row[tid + i*256]; m = fmaxf(m, v[i]); }
    __shared__ float red[256];
    red[tid] = m; __syncthreads();
    #pragma unroll
    for (int s = 128; s > 0; s >>= 1) { if (tid < s) red[tid] = fmaxf(red[tid], red[tid+s]); __syncthreads(); }
    m = red[0]; __syncthreads();
    float sum = 0.f;
    #pragma unroll
    for (int i = 0; i < 8; i++) { v[i] = __expf(v[i] - m); sum += v[i]; }
    red[tid] = sum; __syncthreads();
    #pragma unroll
    for (int s = 128; s > 0; s >>= 1) { if (tid < s) red[tid] += red[tid+s]; __syncthreads(); }
    float inv = 1.0f / red[0];
    const long long base = (long long)blockIdx.x * SEQ;
    #pragma unroll
    for (int i = 0; i < 8; i++) {
        float p = v[i] * inv;
        __half h = __float2half_rn(p);
        Ph[base + tid + i*256] = h;
        Pl[base + tid + i*256] = __float2half_rn(p - __half2float(h));
    }
}

// ---- launch ----
extern "C" void kernel_launch(void* const* d_in, const int* in_sizes, int n_in,
                              void* d_out, int out_size)
{
    const float* X  = (const float*)d_in[0];
    const float* bo = (const float*)d_in[5];
    float* out = (float*)d_out;

    __half *Xhi, *Xlo, *Qhi, *Qlo, *Khi, *Vthi, *Phi, *Plo, *Ohi, *Olo, *Wth;
    float* Sc;
    cudaGetSymbolAddress((void**)&Xhi, g_Xhi);   cudaGetSymbolAddress((void**)&Xlo, g_Xlo);
    cudaGetSymbolAddress((void**)&Wth, g_Wth);
    cudaGetSymbolAddress((void**)&Qhi, g_Qhi);   cudaGetSymbolAddress((void**)&Qlo, g_Qlo);
    cudaGetSymbolAddress((void**)&Khi, g_Khi);
    cudaGetSymbolAddress((void**)&Vthi, g_Vthi);
    cudaGetSymbolAddress((void**)&Sc, g_S);
    cudaGetSymbolAddress((void**)&Phi, g_Phi);   cudaGetSymbolAddress((void**)&Plo, g_Plo);
    cudaGetSymbolAddress((void**)&Ohi, g_Ohi);   cudaGetSymbolAddress((void**)&Olo, g_Olo);

    cudaFuncSetAttribute(gemm_mma<1,false>, cudaFuncAttributeMaxDynamicSharedMemorySize, GEMM_SMEM);
    cudaFuncSetAttribute(gemm_mma<3,false>, cudaFuncAttributeMaxDynamicSharedMemorySize, GEMM_SMEM);
    cudaFuncSetAttribute(gemm_mma<2,false>, cudaFuncAttributeMaxDynamicSharedMemorySize, GEMM_SMEM);
    cudaFuncSetAttribute(gemm_mma<0,false>, cudaFuncAttributeMaxDynamicSharedMemorySize, GEMM_SMEM);
    cudaFuncSetAttribute(gemm_mma<0,true >, cudaFuncAttributeMaxDynamicSharedMemorySize, GEMM_SMEM);

    const size_t wsz = (size_t)DIM * DIM;

    // 1: X split   2: W transpose (hi only)
    split_kernel<<<(MTOT*DIM/4 + 255)/256, 256>>>((const float4*)X,
        (__half2*)Xhi, (__half2*)Xlo, MTOT*DIM/4);
    transpose_h4<<<dim3(32,32,4), dim3(32,8)>>>((const float*)d_in[1], (const float*)d_in[2],
        (const float*)d_in[3], (const float*)d_in[4], Wth);

    // 3-5: Q (hi+lo), K (hi only), Vt (hi only) projections — 2-term
    {
        dim3 g(DIM/256, MTOT/128, 1);
        gemm_mma<1,false><<<g, 256, GEMM_SMEM>>>(Xhi, Xlo, Wth + 0*wsz,
            nullptr, Qhi, Qlo, nullptr, DIM, DIM, 1.0f, 0, 0, 0);
        gemm_mma<3,false><<<g, 256, GEMM_SMEM>>>(Xhi, Xlo, Wth + 1*wsz,
            nullptr, Khi, nullptr, nullptr, DIM, DIM, 1.0f, 0, 0, 0);
        gemm_mma<2,false><<<g, 256, GEMM_SMEM>>>(Xhi, Xlo, Wth + 2*wsz,
            nullptr, Vthi, nullptr, nullptr, DIM, DIM, 1.0f, 0, 0, 0);
    }

    // 6: scores = (Q @ K^T)/32 — 2-term (A=Q corrected, B=Khi)
    {
        dim3 g(SEQ/256, SEQ/128, BATCH);
        gemm_mma<0,false><<<g, 256, GEMM_SMEM>>>(Qhi, Qlo, Khi,
            Sc, nullptr, nullptr, nullptr, DIM, SEQ, 1.0f/32.0f,
            (long long)SEQ, (long long)SEQ, (long long)SEQ * SEQ);
    }

    // 7: softmax + fp16 split -> P hi/lo
    softmax_split_kernel<<<BATCH*SEQ, 256>>>(Sc, Phi, Plo);

    // 8: O = P @ V — 2-term (A=P corrected, B=Vt hi), hi+lo out
    {
        dim3 g(DIM/256, SEQ/128, BATCH);
        gemm_mma<1,false><<<g, 256, GEMM_SMEM>>>(Phi, Plo, Vthi,
            nullptr, Ohi, Olo, nullptr, SEQ, DIM, 1.0f,
            (long long)SEQ, (long long)DIM, (long long)SEQ * DIM);
    }

    // 9: out = O @ Wo + bo — 2-term (A=O corrected, B=Wo hi)
    {
        dim3 g(DIM/256, MTOT/128, 1);
        gemm_mma<0,true><<<g, 256, GEMM_SMEM>>>(Ohi, Olo, Wth + 3*wsz,
            out, nullptr, nullptr, bo, DIM, DIM, 1.0f, 0, 0, 0);
    }
}

// round 16
// speedup vs baseline: 1.8335x; 1.1701x over previous
#include <cuda_runtime.h>
#include <cuda_fp16.h>
#include <cstdint>
#include <math_constants.h>

constexpr int BATCH = 4, SEQ = 2048, DIM = 1024, MTOT = BATCH * SEQ;

// ---- scratch (device globals; 16B-aligned) ----
__device__ __align__(16) __half g_Xhi [(size_t)MTOT * DIM];
__device__ __align__(16) __half g_Xlo [(size_t)MTOT * DIM];
__device__ __align__(16) __half g_Wth [4][(size_t)DIM * DIM];
__device__ __align__(16) __half g_Qhi [(size_t)MTOT * DIM];
__device__ __align__(16) __half g_Qlo [(size_t)MTOT * DIM];
__device__ __align__(16) __half g_Khi [(size_t)MTOT * DIM];
__device__ __align__(16) __half g_Vthi[(size_t)BATCH * DIM * SEQ];
__device__ __align__(16) float  g_S   [(size_t)BATCH * SEQ * SEQ];
__device__ __align__(16) __half g_Phi [(size_t)BATCH * SEQ * SEQ];
__device__ __align__(16) __half g_Ohi [(size_t)MTOT * DIM];

__device__ __forceinline__ uint32_t s2u(const void* p) {
    uint32_t a;
    asm("{ .reg .u64 t; cvta.to.shared.u64 t, %1; cvt.u32.u64 %0, t; }" : "=r"(a) : "l"(p));
    return a;
}
#define CPA16(dst, src) \
    asm volatile("cp.async.cg.shared.global [%0], [%1], 16;" :: "r"(dst), "l"(src) : "memory")
#define LDSM4(r, a) \
    asm volatile("ldmatrix.sync.aligned.m8n8.x4.shared.b16 {%0,%1,%2,%3}, [%4];" \
        : "=r"((r)[0]), "=r"((r)[1]), "=r"((r)[2]), "=r"((r)[3]) : "r"(a))
#define MMA16816(c, a, b0, b1) \
    asm volatile("mma.sync.aligned.m16n8k16.row.col.f32.f16.f16.f32 " \
        "{%0,%1,%2,%3}, {%4,%5,%6,%7}, {%8,%9}, {%0,%1,%2,%3};" \
        : "+f"((c)[0]), "+f"((c)[1]), "+f"((c)[2]), "+f"((c)[3]) \
        : "r"((a)[0]), "r"((a)[1]), "r"((a)[2]), "r"((a)[3]), "r"(b0), "r"(b1))

// ---- GEMM: D[m][n] = sum_k A[m][k]*B[n][k] ----
// TERMS=2: AhBh + AlBh (A corrected).  TERMS=1: AhBh (pure fp16).
// CTA 128x256, 8 warps (2x4), warp tile 64x64, K-chunk 32, 5-stage cp.async,
// one __syncthreads per 64 K (two stages per barrier). ROWB=80 conflict-free.
constexpr int ROWB = 80;
constexpr int R_AH = 0, R_AL = 10240, R_BH = 20480;
constexpr int STAGE_SZ = 40960;
constexpr int NSTAGE = 5;
constexpr int GEMM_SMEM = NSTAGE * STAGE_SZ;      // 204800

// MODE 0: fp32 out (alpha, opt bias). MODE 1: hi+lo out. MODE 2: Vt hi-only out.
// MODE 3: hi-only out.
template<int MODE, int TERMS, bool HASBIAS>
__global__ __launch_bounds__(256, 1)
void gemm_mma(const __half* __restrict__ Ah, const __half* __restrict__ Al,
              const __half* __restrict__ Bh,
              float* __restrict__ Cf,
              __half* __restrict__ Ch, __half* __restrict__ Cl,
              const float* __restrict__ bias,
              int Kd, int ldC, float alpha,
              long long aRowZ, long long bRowZ, long long cOffZ)
{
    extern __shared__ __align__(128) char smem[];
    const uint32_t sb = s2u(smem);
    const int tid = threadIdx.x, wid = tid >> 5, lane = tid & 31;
    const int wm = wid >> 2, wn = wid & 3;
    const int rowBase = blockIdx.y * 128, colBase = blockIdx.x * 256;
    const long long aRow0 = (long long)blockIdx.z * aRowZ + rowBase;
    const long long bRow0 = (long long)blockIdx.z * bRowZ + colBase;

    const int r = tid >> 2, cg = tid & 3;
    const long long rowStep = (long long)Kd * 2;
    const char* pAH = (const char*)Ah + (aRow0 + r) * rowStep + cg * 16;
    const char* pAL = (TERMS == 2) ? (const char*)Al + (aRow0 + r) * rowStep + cg * 16 : nullptr;
    const char* pBH = (const char*)Bh + (bRow0 + r) * rowStep + cg * 16;
    const uint32_t dRow = (uint32_t)(r * ROWB + cg * 16);
    const long long rowStep64 = 64 * rowStep;
    const int nCh = Kd >> 5;

    auto load_stage = [&](int c, int s) {
        const uint32_t d = sb + s * STAGE_SZ + dRow;
        const long long cb = (long long)c * 64;
        CPA16(d + R_AH,             pAH + cb);
        CPA16(d + R_AH + 64 * ROWB, pAH + rowStep64 + cb);
        if (TERMS == 2) {
            CPA16(d + R_AL,             pAL + cb);
            CPA16(d + R_AL + 64 * ROWB, pAL + rowStep64 + cb);
        }
        #pragma unroll
        for (int i = 0; i < 4; i++)          // B: 256 rows
            CPA16(d + R_BH + i * 64 * ROWB, pBH + i * rowStep64 + cb);
        asm volatile("cp.async.commit_group;" ::: "memory");
    };

    const uint32_t aOff = (uint32_t)((wm * 64 + (lane & 7) + ((lane >> 3) & 1) * 8) * ROWB
                                     + ((lane >> 4) * 8) * 2);
    const uint32_t bOff = (uint32_t)((wn * 64 + (lane & 7) + ((lane >> 4) & 1) * 8) * ROWB
                                     + (((lane >> 3) & 1) * 8) * 2);

    float acc[4][8][4];
    #pragma unroll
    for (int i = 0; i < 4; i++)
        #pragma unroll
        for (int j = 0; j < 8; j++)
            #pragma unroll
            for (int q = 0; q < 4; q++) acc[i][j][q] = 0.0f;

    load_stage(0, 0);
    load_stage(1, 1);
    load_stage(2, 2);

    int nc = 3, ps = 3;
    int cs = 0;

    for (int cc = 0; cc < nCh; cc += 2) {
        if (cc + 2 < nCh) asm volatile("cp.async.wait_group 1;" ::: "memory");
        else              asm volatile("cp.async.wait_group 0;" ::: "memory");
        __syncthreads();
        #pragma unroll
        for (int j = 0; j < 2; j++) {
            if (nc < nCh) {
                load_stage(nc, ps);
                nc++;
                ps = (ps == NSTAGE - 1) ? 0 : ps + 1;
            }
        }

        #pragma unroll
        for (int half = 0; half < 2; half++) {
            const uint32_t st = sb + cs * STAGE_SZ;
            #pragma unroll
            for (int k16 = 0; k16 < 2; k16++) {
                uint32_t ah[4][4], al[4][4], bh[4][4];
                #pragma unroll
                for (int mt = 0; mt < 4; mt++) {
                    LDSM4(ah[mt], st + R_AH + aOff + mt * (16 * ROWB) + k16 * 32);
                    if (TERMS == 2)
                        LDSM4(al[mt], st + R_AL + aOff + mt * (16 * ROWB) + k16 * 32);
                }
                #pragma unroll
                for (int j = 0; j < 4; j++)
                    LDSM4(bh[j], st + R_BH + bOff + j * (16 * ROWB) + k16 * 32);
                #pragma unroll
                for (int mt = 0; mt < 4; mt++)
                    #pragma unroll
                    for (int nt = 0; nt < 8; nt++) {
                        const int jj = nt >> 1, hh = (nt & 1) * 2;
                        MMA16816(acc[mt][nt], ah[mt], bh[jj][hh], bh[jj][hh + 1]);
                    }
                if (TERMS == 2) {
                    #pragma unroll
                    for (int mt = 0; mt < 4; mt++)
                        #pragma unroll
                        for (int nt = 0; nt < 8; nt++) {
                            const int jj = nt >> 1, hh = (nt & 1) * 2;
                            MMA16816(acc[mt][nt], al[mt], bh[jj][hh], bh[jj][hh + 1]);
                        }
                }
            }
            cs = (cs == NSTAGE - 1) ? 0 : cs + 1;
        }
    }

    // ---- epilogue ----
    if (MODE == 2) {
        // Vt hi-only: stage [n][m] (256 x 128) in smem, coalesced 16B stores
        const int b = rowBase >> 11;
        const int seq0 = rowBase & 2047;
        const int mloc0 = wm * 64 + (lane >> 2);
        const int nloc0 = wn * 64 + (lane & 3) * 2;
        __half* smt = reinterpret_cast<__half*>(smem);
        constexpr int MP = 136;
        __syncthreads();
        #pragma unroll
        for (int mt = 0; mt < 4; mt++)
            #pragma unroll
            for (int nt = 0; nt < 8; nt++)
                #pragma unroll
                for (int h = 0; h < 2; h++) {
                    const int m = mloc0 + mt * 16 + h * 8;
                    const int n = nloc0 + nt * 8;
                    smt[n * MP + m]       = __float2half_rn(acc[mt][nt][h * 2 + 0] * alpha);
                    smt[(n + 1) * MP + m] = __float2half_rn(acc[mt][nt][h * 2 + 1] * alpha);
                }
        __syncthreads();
        #pragma unroll
        for (int i = 0; i < 16; i++) {
            const int g = tid + i * 256;
            const int n = g >> 4, o = g & 15;
            uint4 val = *reinterpret_cast<const uint4*>(smt + n * MP + o * 8);
            *reinterpret_cast<uint4*>(Ch
                + ((long long)(b * 1024 + colBase + n)) * 2048 + seq0 + o * 8) = val;
        }
    } else {
        const int mBase = rowBase + wm * 64 + (lane >> 2);
        const int nBaseW = colBase + wn * 64 + (lane & 3) * 2;
        #pragma unroll
        for (int mt = 0; mt < 4; mt++)
            #pragma unroll
            for (int nt = 0; nt < 8; nt++) {
                const int n = nBaseW + nt * 8;
                #pragma unroll
                for (int h = 0; h < 2; h++) {
                    const int m = mBase + mt * 16 + h * 8;
                    float v0 = acc[mt][nt][h * 2 + 0] * alpha;
                    float v1 = acc[mt][nt][h * 2 + 1] * alpha;
                    if (MODE == 0) {
                        if (HASBIAS) { v0 += bias[n]; v1 += bias[n + 1]; }
                        float2 w; w.x = v0; w.y = v1;
                        *reinterpret_cast<float2*>(Cf + (long long)blockIdx.z * cOffZ
                            + (long long)m * ldC + n) = w;
                    } else {
                        const long long base = (long long)blockIdx.z * cOffZ
                            + (long long)m * ldC + n;
                        __half h0 = __float2half_rn(v0), h1 = __float2half_rn(v1);
                        __half2 hp; hp.x = h0; hp.y = h1;
                        *reinterpret_cast<__half2*>(Ch + base) = hp;
                        if (MODE == 1) {
                            __half2 lp;
                            lp.x = __float2half_rn(v0 - __half2float(h0));
                            lp.y = __float2half_rn(v1 - __half2float(h1));
                            *reinterpret_cast<__half2*>(Cl + base) = lp;
                        }
                    }
                }
            }
    }
}

// ---- fp32 -> fp16 hi/lo split ----
__global__ __launch_bounds__(256)
void split_kernel(const float4* __restrict__ in, __half2* __restrict__ hi,
                  __half2* __restrict__ lo, int n4)
{
    int i = blockIdx.x * blockDim.x + threadIdx.x;
    if (i >= n4) return;
    float4 v = in[i];
    __half hx = __float2half_rn(v.x), hy = __float2half_rn(v.y);
    __half hz = __float2half_rn(v.z), hw = __float2half_rn(v.w);
    __half2 a, b, c, d;
    a.x = hx; a.y = hy; b.x = hz; b.y = hw;
    c.x = __float2half_rn(v.x - __half2float(hx));
    c.y = __float2half_rn(v.y - __half2float(hy));
    d.x = __float2half_rn(v.z - __half2float(hz));
    d.y = __float2half_rn(v.w - __half2float(hw));
    hi[(size_t)i*2] = a; hi[(size_t)i*2+1] = b;
    lo[(size_t)i*2] = c; lo[(size_t)i*2+1] = d;
}

// ---- all four W[1024][1024] -> Wt hi (transpose), z selects ----
__global__ __launch_bounds__(256)
void transpose_h4(const float* __restrict__ w0, const float* __restrict__ w1,
                  const float* __restrict__ w2, const float* __restrict__ w3,
                  __half* __restrict__ Th)
{
    const float* W = blockIdx.z == 0 ? w0 : blockIdx.z == 1 ? w1 : blockIdx.z == 2 ? w2 : w3;
    __half* oh = Th + (size_t)blockIdx.z * DIM * DIM;
    __shared__ float t[32][33];
    int x = blockIdx.x * 32 + threadIdx.x;
    int y0 = blockIdx.y * 32;
    #pragma unroll
    for (int j = threadIdx.y; j < 32; j += 8)
        t[j][threadIdx.x] = W[(long long)(y0 + j) * DIM + x];
    __syncthreads();
    int xo = y0 + threadIdx.x, yo = blockIdx.x * 32;
    #pragma unroll
    for (int j = threadIdx.y; j < 32; j += 8)
        oh[(long long)(yo + j) * DIM + xo] = __float2half_rn(t[threadIdx.x][j]);
}

// ---- softmax over 2048 cols -> fp16 P (hi only) ----
__global__ __launch_bounds__(256)
void softmax_h_kernel(const float* __restrict__ S, __half* __restrict__ Ph)
{
    const float* row = S + (long long)blockIdx.x * SEQ;
    const int tid = threadIdx.x;
    float v[8], m = -CUDART_INF_F;
    #pragma unroll
    for (int i = 0; i < 8; i++) { v[i] = row[tid + i*256]; m = fmaxf(m, v[i]); }
    __shared__ float red[256];
    red[tid] = m; __syncthreads();
    #pragma unroll
    for (int s = 128; s > 0; s >>= 1) { if (tid < s) red[tid] = fmaxf(red[tid], red[tid+s]); __syncthreads(); }
    m = red[0]; __syncthreads();
    float sum = 0.f;
    #pragma unroll
    for (int i = 0; i < 8; i++) { v[i] = __expf(v[i] - m); sum += v[i]; }
    red[tid] = sum; __syncthreads();
    #pragma unroll
    for (int s = 128; s > 0; s >>= 1) { if (tid < s) red[tid] += red[tid+s]; __syncthreads(); }
    float inv = 1.0f / red[0];
    const long long base = (long long)blockIdx.x * SEQ;
    #pragma unroll
    for (int i = 0; i < 4; i++) {
        __half2 hp;
        hp.x = __float2half_rn(v[2*i]   * inv);
        hp.y = __float2half_rn(v[2*i+1] * inv);
        // v[2i], v[2i+1] are at columns tid+2i*256 and tid+(2i+1)*256 (not adjacent):
        Ph[base + tid + (2*i)*256]   = hp.x;
        Ph[base + tid + (2*i+1)*256] = hp.y;
    }
}

// ---- launch ----
extern "C" void kernel_launch(void* const* d_in, const int* in_sizes, int n_in,
                              void* d_out, int out_size)
{
    const float* X  = (const float*)d_in[0];
    const float* bo = (const float*)d_in[5];
    float* out = (float*)d_out;

    __half *Xhi, *Xlo, *Qhi, *Qlo, *Khi, *Vthi, *Phi, *Ohi, *Wth;
    float* Sc;
    cudaGetSymbolAddress((void**)&Xhi, g_Xhi);   cudaGetSymbolAddress((void**)&Xlo, g_Xlo);
    cudaGetSymbolAddress((void**)&Wth, g_Wth);
    cudaGetSymbolAddress((void**)&Qhi, g_Qhi);   cudaGetSymbolAddress((void**)&Qlo, g_Qlo);
    cudaGetSymbolAddress((void**)&Khi, g_Khi);
    cudaGetSymbolAddress((void**)&Vthi, g_Vthi);
    cudaGetSymbolAddress((void**)&Sc, g_S);
    cudaGetSymbolAddress((void**)&Phi, g_Phi);
    cudaGetSymbolAddress((void**)&Ohi, g_Ohi);

    cudaFuncSetAttribute(gemm_mma<1,2,false>, cudaFuncAttributeMaxDynamicSharedMemorySize, GEMM_SMEM);
    cudaFuncSetAttribute(gemm_mma<3,2,false>, cudaFuncAttributeMaxDynamicSharedMemorySize, GEMM_SMEM);
    cudaFuncSetAttribute(gemm_mma<2,2,false>, cudaFuncAttributeMaxDynamicSharedMemorySize, GEMM_SMEM);
    cudaFuncSetAttribute(gemm_mma<0,2,false>, cudaFuncAttributeMaxDynamicSharedMemorySize, GEMM_SMEM);
    cudaFuncSetAttribute(gemm_mma<3,1,false>, cudaFuncAttributeMaxDynamicSharedMemorySize, GEMM_SMEM);
    cudaFuncSetAttribute(gemm_mma<0,1,true >, cudaFuncAttributeMaxDynamicSharedMemorySize, GEMM_SMEM);

    const size_t wsz = (size_t)DIM * DIM;

    // 1: X split   2: W transpose (hi only)
    split_kernel<<<(MTOT*DIM/4 + 255)/256, 256>>>((const float4*)X,
        (__half2*)Xhi, (__half2*)Xlo, MTOT*DIM/4);
    transpose_h4<<<dim3(32,32,4), dim3(32,8)>>>((const float*)d_in[1], (const float*)d_in[2],
        (const float*)d_in[3], (const float*)d_in[4], Wth);

    // 3-5: Q (hi+lo), K (hi), Vt (hi) projections — 2-term (A=X corrected)
    {
        dim3 g(DIM/256, MTOT/128, 1);
        gemm_mma<1,2,false><<<g, 256, GEMM_SMEM>>>(Xhi, Xlo, Wth + 0*wsz,
            nullptr, Qhi, Qlo, nullptr, DIM, DIM, 1.0f, 0, 0, 0);
        gemm_mma<3,2,false><<<g, 256, GEMM_SMEM>>>(Xhi, Xlo, Wth + 1*wsz,
            nullptr, Khi, nullptr, nullptr, DIM, DIM, 1.0f, 0, 0, 0);
        gemm_mma<2,2,false><<<g, 256, GEMM_SMEM>>>(Xhi, Xlo, Wth + 2*wsz,
            nullptr, Vthi, nullptr, nullptr, DIM, DIM, 1.0f, 0, 0, 0);
    }

    // 6: scores = (Q @ K^T)/32 — 2-term (A=Q corrected, B=Khi)
    {
        dim3 g(SEQ/256, SEQ/128, BATCH);
        gemm_mma<0,2,false><<<g, 256, GEMM_SMEM>>>(Qhi, Qlo, Khi,
            Sc, nullptr, nullptr, nullptr, DIM, SEQ, 1.0f/32.0f,
            (long long)SEQ, (long long)SEQ, (long long)SEQ * SEQ);
    }

    // 7: softmax -> P (hi only)
    softmax_h_kernel<<<BATCH*SEQ, 256>>>(Sc, Phi);

    // 8: O = P @ V — 1-term pure fp16 (B = Vt hi), hi-only out
    {
        dim3 g(DIM/256, SEQ/128, BATCH);
        gemm_mma<3,1,false><<<g, 256, GEMM_SMEM>>>(Phi, nullptr, Vthi,
            nullptr, Ohi, nullptr, nullptr, SEQ, DIM, 1.0f,
            (long long)SEQ, (long long)DIM, (long long)SEQ * DIM);
    }

    // 9: out = O @ Wo + bo — 1-term pure fp16
    {
        dim3 g(DIM/256, MTOT/128, 1);
        gemm_mma<0,1,true><<<g, 256, GEMM_SMEM>>>(Ohi, nullptr, Wth + 3*wsz,
            out, nullptr, nullptr, bo, DIM, DIM, 1.0f, 0, 0, 0);
    }
}

// round 17
// speedup vs baseline: 2.3422x; 1.2775x over previous
#include <cuda_runtime.h>
#include <cuda_fp16.h>
#include <cstdint>
#include <math_constants.h>

constexpr int BATCH = 4, SEQ = 2048, DIM = 1024, MTOT = BATCH * SEQ;

// ---- scratch (device globals; 16B-aligned) ----
__device__ __align__(16) __half g_Xhi [(size_t)MTOT * DIM];
__device__ __align__(16) __half g_Xlo [(size_t)MTOT * DIM];
__device__ __align__(16) __half g_Wth [4][(size_t)DIM * DIM];
__device__ __align__(16) __half g_Qhi [(size_t)MTOT * DIM];
__device__ __align__(16) __half g_Khi [(size_t)MTOT * DIM];
__device__ __align__(16) __half g_Vthi[(size_t)BATCH * DIM * SEQ];
__device__ __align__(16) float  g_S   [(size_t)BATCH * SEQ * SEQ];
__device__ __align__(16) __half g_Phi [(size_t)BATCH * SEQ * SEQ];
__device__ __align__(16) __half g_Ohi [(size_t)MTOT * DIM];

__device__ __forceinline__ uint32_t s2u(const void* p) {
    uint32_t a;
    asm("{ .reg .u64 t; cvta.to.shared.u64 t, %1; cvt.u32.u64 %0, t; }" : "=r"(a) : "l"(p));
    return a;
}
#define CPA16(dst, src) \
    asm volatile("cp.async.cg.shared.global [%0], [%1], 16;" :: "r"(dst), "l"(src) : "memory")
#define LDSM4(r, a) \
    asm volatile("ldmatrix.sync.aligned.m8n8.x4.shared.b16 {%0,%1,%2,%3}, [%4];" \
        : "=r"((r)[0]), "=r"((r)[1]), "=r"((r)[2]), "=r"((r)[3]) : "r"(a))
#define MMA16816(c, a, b0, b1) \
    asm volatile("mma.sync.aligned.m16n8k16.row.col.f32.f16.f16.f32 " \
        "{%0,%1,%2,%3}, {%4,%5,%6,%7}, {%8,%9}, {%0,%1,%2,%3};" \
        : "+f"((c)[0]), "+f"((c)[1]), "+f"((c)[2]), "+f"((c)[3]) \
        : "r"((a)[0]), "r"((a)[1]), "r"((a)[2]), "r"((a)[3]), "r"(b0), "r"(b1))

// ---- GEMM: D[m][n] = sum_k A[m][k]*B[n][k] ----
// TERMS=2: AhBh + AlBh (A corrected).  TERMS=1: AhBh (pure fp16).
// CTA 128x256, 8 warps (2x4), warp tile 64x64, K-chunk 32, 5-stage cp.async,
// one __syncthreads per 64 K (two stages per barrier). ROWB=80 conflict-free.
constexpr int ROWB = 80;
constexpr int R_AH = 0, R_AL = 10240, R_BH = 20480;
constexpr int STAGE_SZ = 40960;
constexpr int NSTAGE = 5;
constexpr int GEMM_SMEM = NSTAGE * STAGE_SZ;      // 204800

// MODE 0: fp32 out (alpha, opt bias). MODE 2: Vt hi-only out. MODE 3: hi-only out.
template<int MODE, int TERMS, bool HASBIAS>
__global__ __launch_bounds__(256, 1)
void gemm_mma(const __half* __restrict__ Ah, const __half* __restrict__ Al,
              const __half* __restrict__ Bh,
              float* __restrict__ Cf,
              __half* __restrict__ Ch,
              const float* __restrict__ bias,
              int Kd, int ldC, float alpha,
              long long aRowZ, long long bRowZ, long long cOffZ)
{
    extern __shared__ __align__(128) char smem[];
    const uint32_t sb = s2u(smem);
    const int tid = threadIdx.x, wid = tid >> 5, lane = tid & 31;
    const int wm = wid >> 2, wn = wid & 3;
    const int rowBase = blockIdx.y * 128, colBase = blockIdx.x * 256;
    const long long aRow0 = (long long)blockIdx.z * aRowZ + rowBase;
    const long long bRow0 = (long long)blockIdx.z * bRowZ + colBase;

    const int r = tid >> 2, cg = tid & 3;
    const long long rowStep = (long long)Kd * 2;
    const char* pAH = (const char*)Ah + (aRow0 + r) * rowStep + cg * 16;
    const char* pAL = (TERMS == 2) ? (const char*)Al + (aRow0 + r) * rowStep + cg * 16 : nullptr;
    const char* pBH = (const char*)Bh + (bRow0 + r) * rowStep + cg * 16;
    const uint32_t dRow = (uint32_t)(r * ROWB + cg * 16);
    const long long rowStep64 = 64 * rowStep;
    const int nCh = Kd >> 5;

    auto load_stage = [&](int c, int s) {
        const uint32_t d = sb + s * STAGE_SZ + dRow;
        const long long cb = (long long)c * 64;
        CPA16(d + R_AH,             pAH + cb);
        CPA16(d + R_AH + 64 * ROWB, pAH + rowStep64 + cb);
        if (TERMS == 2) {
            CPA16(d + R_AL,             pAL + cb);
            CPA16(d + R_AL + 64 * ROWB, pAL + rowStep64 + cb);
        }
        #pragma unroll
        for (int i = 0; i < 4; i++)          // B: 256 rows
            CPA16(d + R_BH + i * 64 * ROWB, pBH + i * rowStep64 + cb);
        asm volatile("cp.async.commit_group;" ::: "memory");
    };

    const uint32_t aOff = (uint32_t)((wm * 64 + (lane & 7) + ((lane >> 3) & 1) * 8) * ROWB
                                     + ((lane >> 4) * 8) * 2);
    const uint32_t bOff = (uint32_t)((wn * 64 + (lane & 7) + ((lane >> 4) & 1) * 8) * ROWB
                                     + (((lane >> 3) & 1) * 8) * 2);

    float acc[4][8][4];
    #pragma unroll
    for (int i = 0; i < 4; i++)
        #pragma unroll
        for (int j = 0; j < 8; j++)
            #pragma unroll
            for (int q = 0; q < 4; q++) acc[i][j][q] = 0.0f;

    load_stage(0, 0);
    load_stage(1, 1);
    load_stage(2, 2);

    int nc = 3, ps = 3;
    int cs = 0;

    for (int cc = 0; cc < nCh; cc += 2) {
        if (cc + 2 < nCh) asm volatile("cp.async.wait_group 1;" ::: "memory");
        else              asm volatile("cp.async.wait_group 0;" ::: "memory");
        __syncthreads();
        #pragma unroll
        for (int j = 0; j < 2; j++) {
            if (nc < nCh) {
                load_stage(nc, ps);
                nc++;
                ps = (ps == NSTAGE - 1) ? 0 : ps + 1;
            }
        }

        #pragma unroll
        for (int half = 0; half < 2; half++) {
            const uint32_t st = sb + cs * STAGE_SZ;
            #pragma unroll
            for (int k16 = 0; k16 < 2; k16++) {
                uint32_t ah[4][4], al[4][4], bh[4][4];
                #pragma unroll
                for (int mt = 0; mt < 4; mt++) {
                    LDSM4(ah[mt], st + R_AH + aOff + mt * (16 * ROWB) + k16 * 32);
                    if (TERMS == 2)
                        LDSM4(al[mt], st + R_AL + aOff + mt * (16 * ROWB) + k16 * 32);
                }
                #pragma unroll
                for (int j = 0; j < 4; j++)
                    LDSM4(bh[j], st + R_BH + bOff + j * (16 * ROWB) + k16 * 32);
                #pragma unroll
                for (int mt = 0; mt < 4; mt++)
                    #pragma unroll
                    for (int nt = 0; nt < 8; nt++) {
                        const int jj = nt >> 1, hh = (nt & 1) * 2;
                        MMA16816(acc[mt][nt], ah[mt], bh[jj][hh], bh[jj][hh + 1]);
                    }
                if (TERMS == 2) {
                    #pragma unroll
                    for (int mt = 0; mt < 4; mt++)
                        #pragma unroll
                        for (int nt = 0; nt < 8; nt++) {
                            const int jj = nt >> 1, hh = (nt & 1) * 2;
                            MMA16816(acc[mt][nt], al[mt], bh[jj][hh], bh[jj][hh + 1]);
                        }
                }
            }
            cs = (cs == NSTAGE - 1) ? 0 : cs + 1;
        }
    }

    // ---- epilogue ----
    if (MODE == 2) {
        // Vt hi-only: stage [n][m] (256 x 128) in smem, coalesced 16B stores
        const int b = rowBase >> 11;
        const int seq0 = rowBase & 2047;
        const int mloc0 = wm * 64 + (lane >> 2);
        const int nloc0 = wn * 64 + (lane & 3) * 2;
        __half* smt = reinterpret_cast<__half*>(smem);
        constexpr int MP = 136;
        __syncthreads();
        #pragma unroll
        for (int mt = 0; mt < 4; mt++)
            #pragma unroll
            for (int nt = 0; nt < 8; nt++)
                #pragma unroll
                for (int h = 0; h < 2; h++) {
                    const int m = mloc0 + mt * 16 + h * 8;
                    const int n = nloc0 + nt * 8;
                    smt[n * MP + m]       = __float2half_rn(acc[mt][nt][h * 2 + 0] * alpha);
                    smt[(n + 1) * MP + m] = __float2half_rn(acc[mt][nt][h * 2 + 1] * alpha);
                }
        __syncthreads();
        #pragma unroll
        for (int i = 0; i < 16; i++) {
            const int g = tid + i * 256;
            const int n = g >> 4, o = g & 15;
            uint4 val = *reinterpret_cast<const uint4*>(smt + n * MP + o * 8);
            *reinterpret_cast<uint4*>(Ch
                + ((long long)(b * 1024 + colBase + n)) * 2048 + seq0 + o * 8) = val;
        }
    } else {
        const int mBase = rowBase + wm * 64 + (lane >> 2);
        const int nBaseW = colBase + wn * 64 + (lane & 3) * 2;
        #pragma unroll
        for (int mt = 0; mt < 4; mt++)
            #pragma unroll
            for (int nt = 0; nt < 8; nt++) {
                const int n = nBaseW + nt * 8;
                #pragma unroll
                for (int h = 0; h < 2; h++) {
                    const int m = mBase + mt * 16 + h * 8;
                    float v0 = acc[mt][nt][h * 2 + 0] * alpha;
                    float v1 = acc[mt][nt][h * 2 + 1] * alpha;
                    if (MODE == 0) {
                        if (HASBIAS) { v0 += bias[n]; v1 += bias[n + 1]; }
                        float2 w; w.x = v0; w.y = v1;
                        *reinterpret_cast<float2*>(Cf + (long long)blockIdx.z * cOffZ
                            + (long long)m * ldC + n) = w;
                    } else {
                        const long long base = (long long)blockIdx.z * cOffZ
                            + (long long)m * ldC + n;
                        __half2 hp;
                        hp.x = __float2half_rn(v0);
                        hp.y = __float2half_rn(v1);
                        *reinterpret_cast<__half2*>(Ch + base) = hp;
                    }
                }
            }
    }
}

// ---- fp32 -> fp16 hi/lo split ----
__global__ __launch_bounds__(256)
void split_kernel(const float4* __restrict__ in, __half2* __restrict__ hi,
                  __half2* __restrict__ lo, int n4)
{
    int i = blockIdx.x * blockDim.x + threadIdx.x;
    if (i >= n4) return;
    float4 v = in[i];
    __half hx = __float2half_rn(v.x), hy = __float2half_rn(v.y);
    __half hz = __float2half_rn(v.z), hw = __float2half_rn(v.w);
    __half2 a, b, c, d;
    a.x = hx; a.y = hy; b.x = hz; b.y = hw;
    c.x = __float2half_rn(v.x - __half2float(hx));
    c.y = __float2half_rn(v.y - __half2float(hy));
    d.x = __float2half_rn(v.z - __half2float(hz));
    d.y = __float2half_rn(v.w - __half2float(hw));
    hi[(size_t)i*2] = a; hi[(size_t)i*2+1] = b;
    lo[(size_t)i*2] = c; lo[(size_t)i*2+1] = d;
}

// ---- all four W[1024][1024] -> Wt hi (transpose), z selects ----
__global__ __launch_bounds__(256)
void transpose_h4(const float* __restrict__ w0, const float* __restrict__ w1,
                  const float* __restrict__ w2, const float* __restrict__ w3,
                  __half* __restrict__ Th)
{
    const float* W = blockIdx.z == 0 ? w0 : blockIdx.z == 1 ? w1 : blockIdx.z == 2 ? w2 : w3;
    __half* oh = Th + (size_t)blockIdx.z * DIM * DIM;
    __shared__ float t[32][33];
    int x = blockIdx.x * 32 + threadIdx.x;
    int y0 = blockIdx.y * 32;
    #pragma unroll
    for (int j = threadIdx.y; j < 32; j += 8)
        t[j][threadIdx.x] = W[(long long)(y0 + j) * DIM + x];
    __syncthreads();
    int xo = y0 + threadIdx.x, yo = blockIdx.x * 32;
    #pragma unroll
    for (int j = threadIdx.y; j < 32; j += 8)
        oh[(long long)(yo + j) * DIM + xo] = __float2half_rn(t[threadIdx.x][j]);
}

// ---- softmax over 2048 cols -> fp16 P (hi only) ----
__global__ __launch_bounds__(256)
void softmax_h_kernel(const float* __restrict__ S, __half* __restrict__ Ph)
{
    const float* row = S + (long long)blockIdx.x * SEQ;
    const int tid = threadIdx.x;
    float v[8], m = -CUDART_INF_F;
    #pragma unroll
    for (int i = 0; i < 8; i++) { v[i] = row[tid + i*256]; m = fmaxf(m, v[i]); }
    __shared__ float red[256];
    red[tid] = m; __syncthreads();
    #pragma unroll
    for (int s = 128; s > 0; s >>= 1) { if (tid < s) red[tid] = fmaxf(red[tid], red[tid+s]); __syncthreads(); }
    m = red[0]; __syncthreads();
    float sum = 0.f;
    #pragma unroll
    for (int i = 0; i < 8; i++) { v[i] = __expf(v[i] - m); sum += v[i]; }
    red[tid] = sum; __syncthreads();
    #pragma unroll
    for (int s = 128; s > 0; s >>= 1) { if (tid < s) red[tid] += red[tid+s]; __syncthreads(); }
    float inv = 1.0f / red[0];
    const long long base = (long long)blockIdx.x * SEQ;
    #pragma unroll
    for (int i = 0; i < 8; i++)
        Ph[base + tid + i*256] = __float2half_rn(v[i] * inv);
}

// ---- launch ----
extern "C" void kernel_launch(void* const* d_in, const int* in_sizes, int n_in,
                              void* d_out, int out_size)
{
    const float* X  = (const float*)d_in[0];
    const float* bo = (const float*)d_in[5];
    float* out = (float*)d_out;

    __half *Xhi, *Xlo, *Qhi, *Khi, *Vthi, *Phi, *Ohi, *Wth;
    float* Sc;
    cudaGetSymbolAddress((void**)&Xhi, g_Xhi);   cudaGetSymbolAddress((void**)&Xlo, g_Xlo);
    cudaGetSymbolAddress((void**)&Wth, g_Wth);
    cudaGetSymbolAddress((void**)&Qhi, g_Qhi);
    cudaGetSymbolAddress((void**)&Khi, g_Khi);
    cudaGetSymbolAddress((void**)&Vthi, g_Vthi);
    cudaGetSymbolAddress((void**)&Sc, g_S);
    cudaGetSymbolAddress((void**)&Phi, g_Phi);
    cudaGetSymbolAddress((void**)&Ohi, g_Ohi);

    cudaFuncSetAttribute(gemm_mma<3,2,false>, cudaFuncAttributeMaxDynamicSharedMemorySize, GEMM_SMEM);
    cudaFuncSetAttribute(gemm_mma<3,1,false>, cudaFuncAttributeMaxDynamicSharedMemorySize, GEMM_SMEM);
    cudaFuncSetAttribute(gemm_mma<2,1,false>, cudaFuncAttributeMaxDynamicSharedMemorySize, GEMM_SMEM);
    cudaFuncSetAttribute(gemm_mma<0,1,false>, cudaFuncAttributeMaxDynamicSharedMemorySize, GEMM_SMEM);
    cudaFuncSetAttribute(gemm_mma<0,1,true >, cudaFuncAttributeMaxDynamicSharedMemorySize, GEMM_SMEM);

    const size_t wsz = (size_t)DIM * DIM;

    // 1: X split   2: W transpose (hi only)
    split_kernel<<<(MTOT*DIM/4 + 255)/256, 256>>>((const float4*)X,
        (__half2*)Xhi, (__half2*)Xlo, MTOT*DIM/4);
    transpose_h4<<<dim3(32,32,4), dim3(32,8)>>>((const float*)d_in[1], (const float*)d_in[2],
        (const float*)d_in[3], (const float*)d_in[4], Wth);

    // 3: Q projection — 2-term (A=X corrected), hi-only out
    // 4-5: K, Vt projections — 1-term pure fp16
    {
        dim3 g(DIM/256, MTOT/128, 1);
        gemm_mma<3,2,false><<<g, 256, GEMM_SMEM>>>(Xhi, Xlo, Wth + 0*wsz,
            nullptr, Qhi, nullptr, DIM, DIM, 1.0f, 0, 0, 0);
        gemm_mma<3,1,false><<<g, 256, GEMM_SMEM>>>(Xhi, nullptr, Wth + 1*wsz,
            nullptr, Khi, nullptr, DIM, DIM, 1.0f, 0, 0, 0);
        gemm_mma<2,1,false><<<g, 256, GEMM_SMEM>>>(Xhi, nullptr, Wth + 2*wsz,
            nullptr, Vthi, nullptr, DIM, DIM, 1.0f, 0, 0, 0);
    }

    // 6: scores = (Q @ K^T)/32 — 1-term pure fp16
    {
        dim3 g(SEQ/256, SEQ/128, BATCH);
        gemm_mma<0,1,false><<<g, 256, GEMM_SMEM>>>(Qhi, nullptr, Khi,
            Sc, nullptr, nullptr, DIM, SEQ, 1.0f/32.0f,
            (long long)SEQ, (long long)SEQ, (long long)SEQ * SEQ);
    }

    // 7: softmax -> P (hi only)
    softmax_h_kernel<<<BATCH*SEQ, 256>>>(Sc, Phi);

    // 8: O = P @ V — 1-term pure fp16, hi-only out
    {
        dim3 g(DIM/256, SEQ/128, BATCH);
        gemm_mma<3,1,false><<<g, 256, GEMM_SMEM>>>(Phi, nullptr, Vthi,
            nullptr, Ohi, nullptr, SEQ, DIM, 1.0f,
            (long long)SEQ, (long long)DIM, (long long)SEQ * DIM);
    }

    // 9: out = O @ Wo + bo — 1-term pure fp16
    {
        dim3 g(DIM/256, MTOT/128, 1);
        gemm_mma<0,1,true><<<g, 256, GEMM_SMEM>>>(Ohi, nullptr, Wth + 3*wsz,
            out, nullptr, bo, DIM, DIM, 1.0f, 0, 0, 0);
    }
}